// round 10
// baseline (speedup 1.0000x reference)
#include <cuda_runtime.h>
#include <math.h>

#define N_ENT 200000
#define N_USR 100000
#define DIM   64
#define E_N   1500000
#define NI_N  1000000
#define N_RELM1 10
#define WPB  8                             // warps per block
#define HPW  2                             // heads per warp (16 lanes each)
#define EBLK (N_ENT / (WPB * HPW))         // 12500 (exact)
#define UBLK (N_USR / (WPB * HPW))         // 6250  (exact)
#define ZBLK 512                           // cnt-rezero blocks appended to hop0 grid

// ---------------- device scratch (no allocation allowed) ----------------
// Invariant: g_cnt_* are all-zero at entry to kernel_launch (zero-init at load;
// hop0 tail blocks re-zero them after scatter each call).
__device__ int   g_remap[16];
__device__ int   g_cnt_ent[N_ENT];
__device__ int   g_off_ent[N_ENT + 1];
__device__ int   g_cnt_usr[N_USR];
__device__ int   g_off_usr[N_USR + 1];
__device__ int   g_packed[E_N];      // tail | (virt<<18)
__device__ int   g_items[NI_N];
__device__ float g_entB[N_ENT * DIM];
__device__ float g_usrB[N_USR * DIM];

// ---------------- helpers ----------------
__device__ __forceinline__ float wsum16(float v) {
    #pragma unroll
    for (int o = 8; o > 0; o >>= 1) v += __shfl_xor_sync(0xffffffffu, v, o);
    return v;
}
__device__ __forceinline__ float dot4(float4 a, float4 b) {
    return a.x * b.x + a.y * b.y + a.z * b.z + a.w * b.w;
}
__device__ __forceinline__ void add4(float4& A, float4 n) {
    A.x += n.x; A.y += n.y; A.z += n.z; A.w += n.w;
}
__device__ __forceinline__ void fma4(float4& A, float s, float4 n) {
    A.x += s * n.x; A.y += s * n.y; A.z += s * n.z; A.w += s * n.w;
}
// squash(A*inv) + base  (16-lane variant)
__device__ __forceinline__ float4 squash_addi4(float4 A, float inv, float4 base) {
    float4 u = make_float4(A.x * inv, A.y * inv, A.z * inv, A.w * inv);
    float sq = wsum16(dot4(u, u));
    float s = __fdividef(sq, (sq + 1.0f) * fmaxf(sqrtf(sq), 1e-12f));
    return make_float4(u.x * s + base.x, u.y * s + base.y,
                       u.z * s + base.z, u.w * s + base.w);
}

// ---------------- preprocessing (3 launches) ----------------

__global__ void __launch_bounds__(256)
hist_both_k(const int* __restrict__ heads, const int* __restrict__ uidx,
            const float* __restrict__ relw, const float* __restrict__ lat) {
    int gi = blockIdx.x * blockDim.x + threadIdx.x;
    if (gi < N_RELM1) {
        float best = -1e30f; int bi = 0;
        for (int v = 0; v < 3; v++) {
            float sdot = 0.f;
            #pragma unroll 1
            for (int k = 0; k < DIM; k++) sdot += relw[gi * DIM + k] * lat[v * DIM + k];
            if (sdot > best) { best = sdot; bi = v; }
        }
        g_remap[gi] = bi;
    }
    int total = E_N + NI_N;
    for (int i = gi; i < total; i += gridDim.x * blockDim.x) {
        if (i < E_N) atomicAdd(&g_cnt_ent[heads[i]], 1);
        else         atomicAdd(&g_cnt_usr[uidx[i - E_N]], 1);
    }
}

__global__ void __launch_bounds__(1024) scan_both_k() {
    int *cnt, *off; int n;
    if (blockIdx.x == 0) { cnt = g_cnt_ent; off = g_off_ent; n = N_ENT; }
    else                 { cnt = g_cnt_usr; off = g_off_usr; n = N_USR; }
    const int tid = threadIdx.x;
    const int lane = tid & 31, wid = tid >> 5;
    __shared__ int wsh[32];
    __shared__ int carry_s;
    if (tid == 0) carry_s = 0;
    __syncthreads();
    for (int base = 0; base < n; base += 1024) {
        int i = base + tid;
        int v = (i < n) ? cnt[i] : 0;
        int x = v;
        #pragma unroll
        for (int o = 1; o < 32; o <<= 1) {
            int t = __shfl_up_sync(0xffffffffu, x, o);
            if (lane >= o) x += t;
        }
        if (lane == 31) wsh[wid] = x;
        __syncthreads();
        if (wid == 0) {
            int y = wsh[lane];
            #pragma unroll
            for (int o = 1; o < 32; o <<= 1) {
                int t = __shfl_up_sync(0xffffffffu, y, o);
                if (lane >= o) y += t;
            }
            wsh[lane] = y;
        }
        __syncthreads();
        int warp_off = (wid > 0) ? wsh[wid - 1] : 0;
        int incl = x + warp_off;
        int carry = carry_s;
        if (i < n) { off[i] = carry + incl - v; cnt[i] = 0; }
        __syncthreads();
        if (tid == 1023) carry_s = carry + incl;
        __syncthreads();
    }
    if (tid == 0) off[n] = carry_s;
}

__global__ void __launch_bounds__(256)
scatter_both_k(const int* __restrict__ heads, const int* __restrict__ tails,
               const int* __restrict__ et,
               const int* __restrict__ uidx, const int* __restrict__ iidx) {
    int total = E_N + NI_N;
    for (int i = blockIdx.x * blockDim.x + threadIdx.x; i < total; i += gridDim.x * blockDim.x) {
        if (i < E_N) {
            int h = heads[i];
            int pos = g_off_ent[h] + atomicAdd(&g_cnt_ent[h], 1);
            int v = g_remap[et[i] - 1];
            g_packed[pos] = tails[i] | (v << 18);
        } else {
            int k = i - E_N;
            int u = uidx[k];
            int pos = g_off_usr[u] + atomicAdd(&g_cnt_usr[u], 1);
            g_items[pos] = iidx[k];
        }
    }
}

// ---------------- fused hop kernel: 2 heads per warp, 16 lanes x float4 ----------------
__global__ void __launch_bounds__(256)
fused_hop_k(const float4* __restrict__ ent_in, const float4* __restrict__ usr_in,
            const float* __restrict__ aggw, int hop, int init,
            const int* __restrict__ off_e, const int* __restrict__ packed,
            const int* __restrict__ off_u, const int* __restrict__ items,
            float4* __restrict__ ent_store, float4* __restrict__ usr_store,
            float4* __restrict__ res_ent, float4* __restrict__ res_usr)
{
    __shared__ float s_d[WPB][32];     // pass-1 dots: [warp][half*16 + j]

    const int wid  = threadIdx.x >> 5;
    const int lane = threadIdx.x & 31;
    const int l16  = lane & 15;
    const int half = lane >> 4;
    float* __restrict__ sd = &s_d[wid][half * 16];

    if (blockIdx.x >= EBLK + UBLK) {
        // cnt re-zero duty (hop0 only): restore the all-zero invariant
        int i = (blockIdx.x - (EBLK + UBLK)) * 256 + threadIdx.x;
        for (; i < N_ENT + N_USR; i += ZBLK * 256) {
            if (i < N_ENT) g_cnt_ent[i] = 0;
            else           g_cnt_usr[i - N_ENT] = 0;
        }
        return;
    }

    if (blockIdx.x < EBLK) {
        // ======================= ENTITY (2 heads / warp) =======================
        int w = (blockIdx.x * WPB + wid) * HPW + half;   // head id, always < N_ENT

        float4 en = ent_in[w * 16 + l16];
        int s = off_e[w], e = off_e[w + 1];
        int deg = e - s;
        int mdeg = max(deg, __shfl_xor_sync(0xffffffffu, deg, 16));  // uniform per warp

        float a0 = aggw[hop * 3 + 0], a1 = aggw[hop * 3 + 1], a2 = aggw[hop * 3 + 2];
        float mx = fmaxf(a0, fmaxf(a1, a2));
        float e0 = __expf(a0 - mx), e1 = __expf(a1 - mx), e2 = __expf(a2 - mx);
        float inv = __fdividef(1.0f, e0 + e1 + e2);
        float w0 = e0 * inv, w1 = e1 * inv, w2 = e2 * inv;

        float4 u30, u31, u32;

        if (mdeg <= 16) {
            // ---------- fast path: own half's edges resident in one register ----------
            int pk = (l16 < deg) ? packed[s + l16] : 0;

            // pass 0
            float4 A0 = {0,0,0,0}, A1 = {0,0,0,0}, A2 = {0,0,0,0};
            int c0 = 0, c1 = 0, c2 = 0;
            for (int j = 0; j < mdeg; j++) {
                int p = __shfl_sync(0xffffffffu, pk, j, 16);
                int t = p & 0x3FFFF, v = p >> 18;
                float4 nt = ent_in[t * 16 + l16];
                if (j < deg) {
                    if (v == 0)      { add4(A0, nt); c0++; }
                    else if (v == 1) { add4(A1, nt); c1++; }
                    else             { add4(A2, nt); c2++; }
                }
            }
            float i0 = __fdividef(1.f, fmaxf((float)c0, 1.f));
            float i1 = __fdividef(1.f, fmaxf((float)c1, 1.f));
            float i2 = __fdividef(1.f, fmaxf((float)c2, 1.f));
            float4 u10 = squash_addi4(A0, i0, en);
            float4 u11 = squash_addi4(A1, i1, en);
            float4 u12 = squash_addi4(A2, i2, en);

            // pass 1: dots cached in sd
            A0 = make_float4(0,0,0,0); A1 = make_float4(0,0,0,0); A2 = make_float4(0,0,0,0);
            for (int j = 0; j < mdeg; j++) {
                int p = __shfl_sync(0xffffffffu, pk, j, 16);
                int t = p & 0x3FFFF, v = p >> 18;
                float4 nt = ent_in[t * 16 + l16];
                float4 uv = (v == 0) ? u10 : ((v == 1) ? u11 : u12);
                float d = wsum16(dot4(uv, nt));
                if (j < deg) {
                    if (l16 == 0) sd[j] = d;
                    if (v == 0)      fma4(A0, d, nt);
                    else if (v == 1) fma4(A1, d, nt);
                    else             fma4(A2, d, nt);
                }
            }
            float4 u20 = squash_addi4(A0, i0, en);
            float4 u21 = squash_addi4(A1, i1, en);
            float4 u22 = squash_addi4(A2, i2, en);

            __syncwarp();

            // pass 2: scale = d1^2 * d2
            A0 = make_float4(0,0,0,0); A1 = make_float4(0,0,0,0); A2 = make_float4(0,0,0,0);
            for (int j = 0; j < mdeg; j++) {
                int p = __shfl_sync(0xffffffffu, pk, j, 16);
                int t = p & 0x3FFFF, v = p >> 18;
                float4 nt = ent_in[t * 16 + l16];
                float4 uB = (v == 0) ? u20 : ((v == 1) ? u21 : u22);
                float pb = wsum16(dot4(uB, nt));
                if (j < deg) {
                    float pa = sd[j];
                    float sc = pa * pa * pb;
                    if (v == 0)      fma4(A0, sc, nt);
                    else if (v == 1) fma4(A1, sc, nt);
                    else             fma4(A2, sc, nt);
                }
            }
            u30 = make_float4(A0.x * i0 + en.x, A0.y * i0 + en.y, A0.z * i0 + en.z, A0.w * i0 + en.w);
            u31 = make_float4(A1.x * i1 + en.x, A1.y * i1 + en.y, A1.z * i1 + en.z, A1.w * i1 + en.w);
            u32 = make_float4(A2.x * i2 + en.x, A2.y * i2 + en.y, A2.z * i2 + en.z, A2.w * i2 + en.w);
        } else {
            // ---------- generic path (rare mdeg > 16) ----------
            float4 A0 = {0,0,0,0}, A1 = {0,0,0,0}, A2 = {0,0,0,0};
            int c0 = 0, c1 = 0, c2 = 0;
            for (int b = 0; b < mdeg; b += 16) {
                int m = min(16, mdeg - b);
                int idx = b + l16;
                int pk = (idx < deg) ? packed[s + idx] : 0;
                for (int j = 0; j < m; j++) {
                    int p = __shfl_sync(0xffffffffu, pk, j, 16);
                    int t = p & 0x3FFFF, v = p >> 18;
                    float4 nt = ent_in[t * 16 + l16];
                    if (b + j < deg) {
                        if (v == 0)      { add4(A0, nt); c0++; }
                        else if (v == 1) { add4(A1, nt); c1++; }
                        else             { add4(A2, nt); c2++; }
                    }
                }
            }
            float i0 = __fdividef(1.f, fmaxf((float)c0, 1.f));
            float i1 = __fdividef(1.f, fmaxf((float)c1, 1.f));
            float i2 = __fdividef(1.f, fmaxf((float)c2, 1.f));
            float4 u10 = squash_addi4(A0, i0, en);
            float4 u11 = squash_addi4(A1, i1, en);
            float4 u12 = squash_addi4(A2, i2, en);

            A0 = make_float4(0,0,0,0); A1 = make_float4(0,0,0,0); A2 = make_float4(0,0,0,0);
            for (int b = 0; b < mdeg; b += 16) {
                int m = min(16, mdeg - b);
                int idx = b + l16;
                int pk = (idx < deg) ? packed[s + idx] : 0;
                for (int j = 0; j < m; j++) {
                    int p = __shfl_sync(0xffffffffu, pk, j, 16);
                    int t = p & 0x3FFFF, v = p >> 18;
                    float4 nt = ent_in[t * 16 + l16];
                    float4 uv = (v == 0) ? u10 : ((v == 1) ? u11 : u12);
                    float d = wsum16(dot4(uv, nt));
                    if (b + j < deg) {
                        if (v == 0)      fma4(A0, d, nt);
                        else if (v == 1) fma4(A1, d, nt);
                        else             fma4(A2, d, nt);
                    }
                }
            }
            float4 u20 = squash_addi4(A0, i0, en);
            float4 u21 = squash_addi4(A1, i1, en);
            float4 u22 = squash_addi4(A2, i2, en);

            A0 = make_float4(0,0,0,0); A1 = make_float4(0,0,0,0); A2 = make_float4(0,0,0,0);
            for (int b = 0; b < mdeg; b += 16) {
                int m = min(16, mdeg - b);
                int idx = b + l16;
                int pk = (idx < deg) ? packed[s + idx] : 0;
                for (int j = 0; j < m; j++) {
                    int p = __shfl_sync(0xffffffffu, pk, j, 16);
                    int t = p & 0x3FFFF, v = p >> 18;
                    float4 nt = ent_in[t * 16 + l16];
                    float4 uA = (v == 0) ? u10 : ((v == 1) ? u11 : u12);
                    float4 uB = (v == 0) ? u20 : ((v == 1) ? u21 : u22);
                    float pa = dot4(uA, nt);
                    float pb = dot4(uB, nt);
                    #pragma unroll
                    for (int o = 8; o > 0; o >>= 1) {
                        pa += __shfl_xor_sync(0xffffffffu, pa, o);
                        pb += __shfl_xor_sync(0xffffffffu, pb, o);
                    }
                    if (b + j < deg) {
                        float sc = pa * pa * pb;
                        if (v == 0)      fma4(A0, sc, nt);
                        else if (v == 1) fma4(A1, sc, nt);
                        else             fma4(A2, sc, nt);
                    }
                }
            }
            u30 = make_float4(A0.x * i0 + en.x, A0.y * i0 + en.y, A0.z * i0 + en.z, A0.w * i0 + en.w);
            u31 = make_float4(A1.x * i1 + en.x, A1.y * i1 + en.y, A1.z * i1 + en.z, A1.w * i1 + en.w);
            u32 = make_float4(A2.x * i2 + en.x, A2.y * i2 + en.y, A2.z * i2 + en.z, A2.w * i2 + en.w);
        }

        // weighted agg + l2norm + residual
        float4 ag = make_float4(w0 * u30.x + w1 * u31.x + w2 * u32.x,
                                w0 * u30.y + w1 * u31.y + w2 * u32.y,
                                w0 * u30.z + w1 * u31.z + w2 * u32.z,
                                w0 * u30.w + w1 * u31.w + w2 * u32.w);
        float sq = wsum16(dot4(ag, ag));
        float in2 = __fdividef(1.0f, fmaxf(sqrtf(sq), 1e-12f));
        float4 o = make_float4(ag.x * in2, ag.y * in2, ag.z * in2, ag.w * in2);
        if (ent_store) ent_store[w * 16 + l16] = o;
        float4 r;
        if (init) r = make_float4(en.x + o.x, en.y + o.y, en.z + o.z, en.w + o.w);
        else {
            r = res_ent[w * 16 + l16];
            r.x += o.x; r.y += o.y; r.z += o.z; r.w += o.w;
        }
        res_ent[w * 16 + l16] = r;

    } else {
        // ======================= USER (2 users / warp) =======================
        int w = ((blockIdx.x - EBLK) * WPB + wid) * HPW + half;   // always < N_USR

        float4 un = usr_in[w * 16 + l16];
        int s = off_u[w], e = off_u[w + 1];
        int deg = e - s;
        int mdeg = max(deg, __shfl_xor_sync(0xffffffffu, deg, 16));
        float invd = __fdividef(1.f, fmaxf((float)deg, 1.f));
        float4 u3;

        if (mdeg <= 16) {
            // ---------- fast path ----------
            int it = (l16 < deg) ? items[s + l16] : 0;

            float4 A = {0,0,0,0};
            for (int j = 0; j < mdeg; j++) {
                int t = __shfl_sync(0xffffffffu, it, j, 16);
                float4 nt = ent_in[t * 16 + l16];
                if (j < deg) add4(A, nt);
            }
            float4 u1 = squash_addi4(A, invd, un);

            A = make_float4(0,0,0,0);
            for (int j = 0; j < mdeg; j++) {
                int t = __shfl_sync(0xffffffffu, it, j, 16);
                float4 nt = ent_in[t * 16 + l16];
                float d = wsum16(dot4(u1, nt));
                if (j < deg) fma4(A, d, nt);
            }
            float4 u2 = squash_addi4(A, invd, un);

            A = make_float4(0,0,0,0);
            for (int j = 0; j < mdeg; j++) {
                int t = __shfl_sync(0xffffffffu, it, j, 16);
                float4 nt = ent_in[t * 16 + l16];
                float d = wsum16(dot4(u2, nt));
                if (j < deg) fma4(A, d, nt);
            }
            u3 = make_float4(A.x * invd + un.x, A.y * invd + un.y,
                             A.z * invd + un.z, A.w * invd + un.w);
        } else {
            // ---------- generic path ----------
            float4 A = {0,0,0,0};
            for (int b = 0; b < mdeg; b += 16) {
                int m = min(16, mdeg - b);
                int idx = b + l16;
                int it = (idx < deg) ? items[s + idx] : 0;
                for (int j = 0; j < m; j++) {
                    int t = __shfl_sync(0xffffffffu, it, j, 16);
                    float4 nt = ent_in[t * 16 + l16];
                    if (b + j < deg) add4(A, nt);
                }
            }
            float4 u1 = squash_addi4(A, invd, un);

            A = make_float4(0,0,0,0);
            for (int b = 0; b < mdeg; b += 16) {
                int m = min(16, mdeg - b);
                int idx = b + l16;
                int it = (idx < deg) ? items[s + idx] : 0;
                for (int j = 0; j < m; j++) {
                    int t = __shfl_sync(0xffffffffu, it, j, 16);
                    float4 nt = ent_in[t * 16 + l16];
                    float d = wsum16(dot4(u1, nt));
                    if (b + j < deg) fma4(A, d, nt);
                }
            }
            float4 u2 = squash_addi4(A, invd, un);

            A = make_float4(0,0,0,0);
            for (int b = 0; b < mdeg; b += 16) {
                int m = min(16, mdeg - b);
                int idx = b + l16;
                int it = (idx < deg) ? items[s + idx] : 0;
                for (int j = 0; j < m; j++) {
                    int t = __shfl_sync(0xffffffffu, it, j, 16);
                    float4 nt = ent_in[t * 16 + l16];
                    float d = wsum16(dot4(u2, nt));
                    if (b + j < deg) fma4(A, d, nt);
                }
            }
            u3 = make_float4(A.x * invd + un.x, A.y * invd + un.y,
                             A.z * invd + un.z, A.w * invd + un.w);
        }

        float sq = wsum16(dot4(u3, u3));
        float in2 = __fdividef(1.0f, fmaxf(sqrtf(sq), 1e-12f));
        float4 o = make_float4(u3.x * in2, u3.y * in2, u3.z * in2, u3.w * in2);
        if (usr_store) usr_store[w * 16 + l16] = o;
        float4 r;
        if (init) r = make_float4(un.x + o.x, un.y + o.y, un.z + o.z, un.w + o.w);
        else {
            r = res_usr[w * 16 + l16];
            r.x += o.x; r.y += o.y; r.z += o.z; r.w += o.w;
        }
        res_usr[w * 16 + l16] = r;
    }
}

// ---------------- launch (5 launches) ----------------
extern "C" void kernel_launch(void* const* d_in, const int* in_sizes, int n_in,
                              void* d_out, int out_size) {
    const float* entity_emb = (const float*)d_in[0];
    const float* user_emb   = (const float*)d_in[1];
    const float* latent     = (const float*)d_in[2];
    const float* relw       = (const float*)d_in[3];
    const float* aggw       = (const float*)d_in[4];
    const int*   eidx       = (const int*)d_in[5];   // [2,E]: head row, then tail row
    const int*   etype      = (const int*)d_in[6];
    const int*   uidx       = (const int*)d_in[7];
    const int*   iidx       = (const int*)d_in[8];
    float* out = (float*)d_out;

    int *p_off_ent, *p_off_usr, *p_packed, *p_items;
    float *p_entB, *p_usrB;
    cudaGetSymbolAddress((void**)&p_off_ent, g_off_ent);
    cudaGetSymbolAddress((void**)&p_off_usr, g_off_usr);
    cudaGetSymbolAddress((void**)&p_packed,  g_packed);
    cudaGetSymbolAddress((void**)&p_items,   g_items);
    cudaGetSymbolAddress((void**)&p_entB,    g_entB);
    cudaGetSymbolAddress((void**)&p_usrB,    g_usrB);

    hist_both_k<<<2048, 256>>>(eidx, uidx, relw, latent);                    // #0
    scan_both_k<<<2, 1024>>>();                                              // #1
    scatter_both_k<<<2048, 256>>>(eidx, eidx + E_N, etype, uidx, iidx);      // #2

    float4* res_e = (float4*)out;
    float4* res_u = (float4*)(out + (size_t)N_ENT * DIM);

    // hop 0 (#3): base embeddings in; init residual; ZBLK tail blocks re-zero cnt
    fused_hop_k<<<EBLK + UBLK + ZBLK, 256>>>(
        (const float4*)entity_emb, (const float4*)user_emb, aggw, 0, 1,
        p_off_ent, p_packed, p_off_usr, p_items,
        (float4*)p_entB, (float4*)p_usrB, res_e, res_u);

    // hop 1 (#4): hop-0 outputs in; accumulate residual only
    fused_hop_k<<<EBLK + UBLK, 256>>>(
        (const float4*)p_entB, (const float4*)p_usrB, aggw, 1, 0,
        p_off_ent, p_packed, p_off_usr, p_items,
        nullptr, nullptr, res_e, res_u);
}

// round 13
// speedup vs baseline: 1.1821x; 1.1821x over previous
#include <cuda_runtime.h>
#include <math.h>

#define N_ENT 200000
#define N_USR 100000
#define DIM   64
#define E_N   1500000
#define NI_N  1000000
#define N_RELM1 10
#define WPB  8                             // warps per block
#define HPW  2                             // heads per warp (16 lanes each)
#define EBLK (N_ENT / (WPB * HPW))         // 12500 (exact)
#define UBLK (N_USR / (WPB * HPW))         // 6250  (exact)
#define ZBLK 512                           // cnt-rezero blocks appended to hop0 grid

// ---------------- device scratch (no allocation allowed) ----------------
// Invariant: g_cnt_* are all-zero at entry to kernel_launch (zero-init at load;
// hop0 tail blocks re-zero them after scatter each call).
__device__ int   g_remap[16];
__device__ int   g_cnt_ent[N_ENT];
__device__ int   g_off_ent[N_ENT + 1];
__device__ int   g_cnt_usr[N_USR];
__device__ int   g_off_usr[N_USR + 1];
__device__ int   g_packed[E_N];      // tail | (virt<<18)
__device__ int   g_items[NI_N];
__device__ float g_entB[N_ENT * DIM];
__device__ float g_usrB[N_USR * DIM];

// ---------------- helpers ----------------
__device__ __forceinline__ float wsum16(float v) {
    #pragma unroll
    for (int o = 8; o > 0; o >>= 1) v += __shfl_xor_sync(0xffffffffu, v, o);
    return v;
}
__device__ __forceinline__ float dot4(float4 a, float4 b) {
    return a.x * b.x + a.y * b.y + a.z * b.z + a.w * b.w;
}
__device__ __forceinline__ void add4(float4& A, float4 n) {
    A.x += n.x; A.y += n.y; A.z += n.z; A.w += n.w;
}
__device__ __forceinline__ void fma4(float4& A, float s, float4 n) {
    A.x += s * n.x; A.y += s * n.y; A.z += s * n.z; A.w += s * n.w;
}
// squash(A*inv) + base  (16-lane variant)
__device__ __forceinline__ float4 squash_addi4(float4 A, float inv, float4 base) {
    float4 u = make_float4(A.x * inv, A.y * inv, A.z * inv, A.w * inv);
    float sq = wsum16(dot4(u, u));
    float s = __fdividef(sq, (sq + 1.0f) * fmaxf(sqrtf(sq), 1e-12f));
    return make_float4(u.x * s + base.x, u.y * s + base.y,
                       u.z * s + base.z, u.w * s + base.w);
}

// ---------------- preprocessing (3 launches) ----------------

__global__ void __launch_bounds__(256)
hist_both_k(const int* __restrict__ heads, const int* __restrict__ uidx,
            const float* __restrict__ relw, const float* __restrict__ lat) {
    int gi = blockIdx.x * blockDim.x + threadIdx.x;
    if (gi < N_RELM1) {
        float best = -1e30f; int bi = 0;
        for (int v = 0; v < 3; v++) {
            float sdot = 0.f;
            #pragma unroll 1
            for (int k = 0; k < DIM; k++) sdot += relw[gi * DIM + k] * lat[v * DIM + k];
            if (sdot > best) { best = sdot; bi = v; }
        }
        g_remap[gi] = bi;
    }
    int total = E_N + NI_N;
    for (int i = gi; i < total; i += gridDim.x * blockDim.x) {
        if (i < E_N) atomicAdd(&g_cnt_ent[heads[i]], 1);
        else         atomicAdd(&g_cnt_usr[uidx[i - E_N]], 1);
    }
}

__global__ void __launch_bounds__(1024) scan_both_k() {
    int *cnt, *off; int n;
    if (blockIdx.x == 0) { cnt = g_cnt_ent; off = g_off_ent; n = N_ENT; }
    else                 { cnt = g_cnt_usr; off = g_off_usr; n = N_USR; }
    const int tid = threadIdx.x;
    const int lane = tid & 31, wid = tid >> 5;
    __shared__ int wsh[32];
    __shared__ int carry_s;
    if (tid == 0) carry_s = 0;
    __syncthreads();
    for (int base = 0; base < n; base += 1024) {
        int i = base + tid;
        int v = (i < n) ? cnt[i] : 0;
        int x = v;
        #pragma unroll
        for (int o = 1; o < 32; o <<= 1) {
            int t = __shfl_up_sync(0xffffffffu, x, o);
            if (lane >= o) x += t;
        }
        if (lane == 31) wsh[wid] = x;
        __syncthreads();
        if (wid == 0) {
            int y = wsh[lane];
            #pragma unroll
            for (int o = 1; o < 32; o <<= 1) {
                int t = __shfl_up_sync(0xffffffffu, y, o);
                if (lane >= o) y += t;
            }
            wsh[lane] = y;
        }
        __syncthreads();
        int warp_off = (wid > 0) ? wsh[wid - 1] : 0;
        int incl = x + warp_off;
        int carry = carry_s;
        if (i < n) { off[i] = carry + incl - v; cnt[i] = 0; }
        __syncthreads();
        if (tid == 1023) carry_s = carry + incl;
        __syncthreads();
    }
    if (tid == 0) off[n] = carry_s;
}

__global__ void __launch_bounds__(256)
scatter_both_k(const int* __restrict__ heads, const int* __restrict__ tails,
               const int* __restrict__ et,
               const int* __restrict__ uidx, const int* __restrict__ iidx) {
    int total = E_N + NI_N;
    for (int i = blockIdx.x * blockDim.x + threadIdx.x; i < total; i += gridDim.x * blockDim.x) {
        if (i < E_N) {
            int h = heads[i];
            int pos = g_off_ent[h] + atomicAdd(&g_cnt_ent[h], 1);
            int v = g_remap[et[i] - 1];
            g_packed[pos] = tails[i] | (v << 18);
        } else {
            int k = i - E_N;
            int u = uidx[k];
            int pos = g_off_usr[u] + atomicAdd(&g_cnt_usr[u], 1);
            g_items[pos] = iidx[k];
        }
    }
}

// ---------------- fused hop kernel: 2 heads per warp, 16 lanes x float4 ----------------
// __launch_bounds__(256, 4): cap at 64 regs/thread to hold 4 blocks/SM (occupancy
// was the R10 limiter: 77 regs -> 28.8% occ -> latency-exposed despite halved instrs).
__global__ void __launch_bounds__(256, 4)
fused_hop_k(const float4* __restrict__ ent_in, const float4* __restrict__ usr_in,
            const float* __restrict__ aggw, int hop, int init,
            const int* __restrict__ off_e, const int* __restrict__ packed,
            const int* __restrict__ off_u, const int* __restrict__ items,
            float4* __restrict__ ent_store, float4* __restrict__ usr_store,
            float4* __restrict__ res_ent, float4* __restrict__ res_usr)
{
    __shared__ float s_d[WPB][32];     // pass-1 dots: [warp][half*16 + j]

    const int wid  = threadIdx.x >> 5;
    const int lane = threadIdx.x & 31;
    const int l16  = lane & 15;
    const int half = lane >> 4;
    float* __restrict__ sd = &s_d[wid][half * 16];

    if (blockIdx.x >= EBLK + UBLK) {
        // cnt re-zero duty (hop0 only): restore the all-zero invariant
        int i = (blockIdx.x - (EBLK + UBLK)) * 256 + threadIdx.x;
        for (; i < N_ENT + N_USR; i += ZBLK * 256) {
            if (i < N_ENT) g_cnt_ent[i] = 0;
            else           g_cnt_usr[i - N_ENT] = 0;
        }
        return;
    }

    if (blockIdx.x < EBLK) {
        // ======================= ENTITY (2 heads / warp) =======================
        int w = (blockIdx.x * WPB + wid) * HPW + half;   // head id, always < N_ENT

        float4 en = ent_in[w * 16 + l16];
        int s = off_e[w], e = off_e[w + 1];
        int deg = e - s;
        int mdeg = max(deg, __shfl_xor_sync(0xffffffffu, deg, 16));  // uniform per warp

        float a0 = aggw[hop * 3 + 0], a1 = aggw[hop * 3 + 1], a2 = aggw[hop * 3 + 2];
        float mx = fmaxf(a0, fmaxf(a1, a2));
        float e0 = __expf(a0 - mx), e1 = __expf(a1 - mx), e2 = __expf(a2 - mx);
        float inv = __fdividef(1.0f, e0 + e1 + e2);
        float w0 = e0 * inv, w1 = e1 * inv, w2 = e2 * inv;

        float4 u30, u31, u32;

        if (mdeg <= 16) {
            // ---------- fast path: own half's edges resident in one register ----------
            int pk = (l16 < deg) ? packed[s + l16] : 0;

            // pass 0
            float4 A0 = {0,0,0,0}, A1 = {0,0,0,0}, A2 = {0,0,0,0};
            int c0 = 0, c1 = 0, c2 = 0;
            for (int j = 0; j < mdeg; j++) {
                int p = __shfl_sync(0xffffffffu, pk, j, 16);
                int t = p & 0x3FFFF, v = p >> 18;
                float4 nt = ent_in[t * 16 + l16];
                if (j < deg) {
                    if (v == 0)      { add4(A0, nt); c0++; }
                    else if (v == 1) { add4(A1, nt); c1++; }
                    else             { add4(A2, nt); c2++; }
                }
            }
            float i0 = __fdividef(1.f, fmaxf((float)c0, 1.f));
            float i1 = __fdividef(1.f, fmaxf((float)c1, 1.f));
            float i2 = __fdividef(1.f, fmaxf((float)c2, 1.f));
            float4 u10 = squash_addi4(A0, i0, en);
            float4 u11 = squash_addi4(A1, i1, en);
            float4 u12 = squash_addi4(A2, i2, en);

            // pass 1: dots cached in sd
            A0 = make_float4(0,0,0,0); A1 = make_float4(0,0,0,0); A2 = make_float4(0,0,0,0);
            for (int j = 0; j < mdeg; j++) {
                int p = __shfl_sync(0xffffffffu, pk, j, 16);
                int t = p & 0x3FFFF, v = p >> 18;
                float4 nt = ent_in[t * 16 + l16];
                float4 uv = (v == 0) ? u10 : ((v == 1) ? u11 : u12);
                float d = wsum16(dot4(uv, nt));
                if (j < deg) {
                    if (l16 == 0) sd[j] = d;
                    if (v == 0)      fma4(A0, d, nt);
                    else if (v == 1) fma4(A1, d, nt);
                    else             fma4(A2, d, nt);
                }
            }
            float4 u20 = squash_addi4(A0, i0, en);
            float4 u21 = squash_addi4(A1, i1, en);
            float4 u22 = squash_addi4(A2, i2, en);

            __syncwarp();

            // pass 2: scale = d1^2 * d2 (d1 from sd; u1x dead here)
            A0 = make_float4(0,0,0,0); A1 = make_float4(0,0,0,0); A2 = make_float4(0,0,0,0);
            for (int j = 0; j < mdeg; j++) {
                int p = __shfl_sync(0xffffffffu, pk, j, 16);
                int t = p & 0x3FFFF, v = p >> 18;
                float4 nt = ent_in[t * 16 + l16];
                float4 uB = (v == 0) ? u20 : ((v == 1) ? u21 : u22);
                float pb = wsum16(dot4(uB, nt));
                if (j < deg) {
                    float pa = sd[j];
                    float sc = pa * pa * pb;
                    if (v == 0)      fma4(A0, sc, nt);
                    else if (v == 1) fma4(A1, sc, nt);
                    else             fma4(A2, sc, nt);
                }
            }
            u30 = make_float4(A0.x * i0 + en.x, A0.y * i0 + en.y, A0.z * i0 + en.z, A0.w * i0 + en.w);
            u31 = make_float4(A1.x * i1 + en.x, A1.y * i1 + en.y, A1.z * i1 + en.z, A1.w * i1 + en.w);
            u32 = make_float4(A2.x * i2 + en.x, A2.y * i2 + en.y, A2.z * i2 + en.z, A2.w * i2 + en.w);
        } else {
            // ---------- generic path (rare mdeg > 16) ----------
            float4 A0 = {0,0,0,0}, A1 = {0,0,0,0}, A2 = {0,0,0,0};
            int c0 = 0, c1 = 0, c2 = 0;
            for (int b = 0; b < mdeg; b += 16) {
                int m = min(16, mdeg - b);
                int idx = b + l16;
                int pk = (idx < deg) ? packed[s + idx] : 0;
                for (int j = 0; j < m; j++) {
                    int p = __shfl_sync(0xffffffffu, pk, j, 16);
                    int t = p & 0x3FFFF, v = p >> 18;
                    float4 nt = ent_in[t * 16 + l16];
                    if (b + j < deg) {
                        if (v == 0)      { add4(A0, nt); c0++; }
                        else if (v == 1) { add4(A1, nt); c1++; }
                        else             { add4(A2, nt); c2++; }
                    }
                }
            }
            float i0 = __fdividef(1.f, fmaxf((float)c0, 1.f));
            float i1 = __fdividef(1.f, fmaxf((float)c1, 1.f));
            float i2 = __fdividef(1.f, fmaxf((float)c2, 1.f));
            float4 u10 = squash_addi4(A0, i0, en);
            float4 u11 = squash_addi4(A1, i1, en);
            float4 u12 = squash_addi4(A2, i2, en);

            A0 = make_float4(0,0,0,0); A1 = make_float4(0,0,0,0); A2 = make_float4(0,0,0,0);
            for (int b = 0; b < mdeg; b += 16) {
                int m = min(16, mdeg - b);
                int idx = b + l16;
                int pk = (idx < deg) ? packed[s + idx] : 0;
                for (int j = 0; j < m; j++) {
                    int p = __shfl_sync(0xffffffffu, pk, j, 16);
                    int t = p & 0x3FFFF, v = p >> 18;
                    float4 nt = ent_in[t * 16 + l16];
                    float4 uv = (v == 0) ? u10 : ((v == 1) ? u11 : u12);
                    float d = wsum16(dot4(uv, nt));
                    if (b + j < deg) {
                        if (v == 0)      fma4(A0, d, nt);
                        else if (v == 1) fma4(A1, d, nt);
                        else             fma4(A2, d, nt);
                    }
                }
            }
            float4 u20 = squash_addi4(A0, i0, en);
            float4 u21 = squash_addi4(A1, i1, en);
            float4 u22 = squash_addi4(A2, i2, en);

            A0 = make_float4(0,0,0,0); A1 = make_float4(0,0,0,0); A2 = make_float4(0,0,0,0);
            for (int b = 0; b < mdeg; b += 16) {
                int m = min(16, mdeg - b);
                int idx = b + l16;
                int pk = (idx < deg) ? packed[s + idx] : 0;
                for (int j = 0; j < m; j++) {
                    int p = __shfl_sync(0xffffffffu, pk, j, 16);
                    int t = p & 0x3FFFF, v = p >> 18;
                    float4 nt = ent_in[t * 16 + l16];
                    float4 uA = (v == 0) ? u10 : ((v == 1) ? u11 : u12);
                    float4 uB = (v == 0) ? u20 : ((v == 1) ? u21 : u22);
                    float pa = dot4(uA, nt);
                    float pb = dot4(uB, nt);
                    #pragma unroll
                    for (int o = 8; o > 0; o >>= 1) {
                        pa += __shfl_xor_sync(0xffffffffu, pa, o);
                        pb += __shfl_xor_sync(0xffffffffu, pb, o);
                    }
                    if (b + j < deg) {
                        float sc = pa * pa * pb;
                        if (v == 0)      fma4(A0, sc, nt);
                        else if (v == 1) fma4(A1, sc, nt);
                        else             fma4(A2, sc, nt);
                    }
                }
            }
            u30 = make_float4(A0.x * i0 + en.x, A0.y * i0 + en.y, A0.z * i0 + en.z, A0.w * i0 + en.w);
            u31 = make_float4(A1.x * i1 + en.x, A1.y * i1 + en.y, A1.z * i1 + en.z, A1.w * i1 + en.w);
            u32 = make_float4(A2.x * i2 + en.x, A2.y * i2 + en.y, A2.z * i2 + en.z, A2.w * i2 + en.w);
        }

        // weighted agg + l2norm + residual
        float4 ag = make_float4(w0 * u30.x + w1 * u31.x + w2 * u32.x,
                                w0 * u30.y + w1 * u31.y + w2 * u32.y,
                                w0 * u30.z + w1 * u31.z + w2 * u32.z,
                                w0 * u30.w + w1 * u31.w + w2 * u32.w);
        float sq = wsum16(dot4(ag, ag));
        float in2 = __fdividef(1.0f, fmaxf(sqrtf(sq), 1e-12f));
        float4 o = make_float4(ag.x * in2, ag.y * in2, ag.z * in2, ag.w * in2);
        if (ent_store) ent_store[w * 16 + l16] = o;
        float4 r;
        if (init) r = make_float4(en.x + o.x, en.y + o.y, en.z + o.z, en.w + o.w);
        else {
            r = res_ent[w * 16 + l16];
            r.x += o.x; r.y += o.y; r.z += o.z; r.w += o.w;
        }
        res_ent[w * 16 + l16] = r;

    } else {
        // ======================= USER (2 users / warp) =======================
        int w = ((blockIdx.x - EBLK) * WPB + wid) * HPW + half;   // always < N_USR

        float4 un = usr_in[w * 16 + l16];
        int s = off_u[w], e = off_u[w + 1];
        int deg = e - s;
        int mdeg = max(deg, __shfl_xor_sync(0xffffffffu, deg, 16));
        float invd = __fdividef(1.f, fmaxf((float)deg, 1.f));
        float4 u3;

        if (mdeg <= 16) {
            // ---------- fast path ----------
            int it = (l16 < deg) ? items[s + l16] : 0;

            float4 A = {0,0,0,0};
            for (int j = 0; j < mdeg; j++) {
                int t = __shfl_sync(0xffffffffu, it, j, 16);
                float4 nt = ent_in[t * 16 + l16];
                if (j < deg) add4(A, nt);
            }
            float4 u1 = squash_addi4(A, invd, un);

            A = make_float4(0,0,0,0);
            for (int j = 0; j < mdeg; j++) {
                int t = __shfl_sync(0xffffffffu, it, j, 16);
                float4 nt = ent_in[t * 16 + l16];
                float d = wsum16(dot4(u1, nt));
                if (j < deg) fma4(A, d, nt);
            }
            float4 u2 = squash_addi4(A, invd, un);

            A = make_float4(0,0,0,0);
            for (int j = 0; j < mdeg; j++) {
                int t = __shfl_sync(0xffffffffu, it, j, 16);
                float4 nt = ent_in[t * 16 + l16];
                float d = wsum16(dot4(u2, nt));
                if (j < deg) fma4(A, d, nt);
            }
            u3 = make_float4(A.x * invd + un.x, A.y * invd + un.y,
                             A.z * invd + un.z, A.w * invd + un.w);
        } else {
            // ---------- generic path ----------
            float4 A = {0,0,0,0};
            for (int b = 0; b < mdeg; b += 16) {
                int m = min(16, mdeg - b);
                int idx = b + l16;
                int it = (idx < deg) ? items[s + idx] : 0;
                for (int j = 0; j < m; j++) {
                    int t = __shfl_sync(0xffffffffu, it, j, 16);
                    float4 nt = ent_in[t * 16 + l16];
                    if (b + j < deg) add4(A, nt);
                }
            }
            float4 u1 = squash_addi4(A, invd, un);

            A = make_float4(0,0,0,0);
            for (int b = 0; b < mdeg; b += 16) {
                int m = min(16, mdeg - b);
                int idx = b + l16;
                int it = (idx < deg) ? items[s + idx] : 0;
                for (int j = 0; j < m; j++) {
                    int t = __shfl_sync(0xffffffffu, it, j, 16);
                    float4 nt = ent_in[t * 16 + l16];
                    float d = wsum16(dot4(u1, nt));
                    if (b + j < deg) fma4(A, d, nt);
                }
            }
            float4 u2 = squash_addi4(A, invd, un);

            A = make_float4(0,0,0,0);
            for (int b = 0; b < mdeg; b += 16) {
                int m = min(16, mdeg - b);
                int idx = b + l16;
                int it = (idx < deg) ? items[s + idx] : 0;
                for (int j = 0; j < m; j++) {
                    int t = __shfl_sync(0xffffffffu, it, j, 16);
                    float4 nt = ent_in[t * 16 + l16];
                    float d = wsum16(dot4(u2, nt));
                    if (b + j < deg) fma4(A, d, nt);
                }
            }
            u3 = make_float4(A.x * invd + un.x, A.y * invd + un.y,
                             A.z * invd + un.z, A.w * invd + un.w);
        }

        float sq = wsum16(dot4(u3, u3));
        float in2 = __fdividef(1.0f, fmaxf(sqrtf(sq), 1e-12f));
        float4 o = make_float4(u3.x * in2, u3.y * in2, u3.z * in2, u3.w * in2);
        if (usr_store) usr_store[w * 16 + l16] = o;
        float4 r;
        if (init) r = make_float4(un.x + o.x, un.y + o.y, un.z + o.z, un.w + o.w);
        else {
            r = res_usr[w * 16 + l16];
            r.x += o.x; r.y += o.y; r.z += o.z; r.w += o.w;
        }
        res_usr[w * 16 + l16] = r;
    }
}

// ---------------- launch (5 launches) ----------------
extern "C" void kernel_launch(void* const* d_in, const int* in_sizes, int n_in,
                              void* d_out, int out_size) {
    const float* entity_emb = (const float*)d_in[0];
    const float* user_emb   = (const float*)d_in[1];
    const float* latent     = (const float*)d_in[2];
    const float* relw       = (const float*)d_in[3];
    const float* aggw       = (const float*)d_in[4];
    const int*   eidx       = (const int*)d_in[5];   // [2,E]: head row, then tail row
    const int*   etype      = (const int*)d_in[6];
    const int*   uidx       = (const int*)d_in[7];
    const int*   iidx       = (const int*)d_in[8];
    float* out = (float*)d_out;

    int *p_off_ent, *p_off_usr, *p_packed, *p_items;
    float *p_entB, *p_usrB;
    cudaGetSymbolAddress((void**)&p_off_ent, g_off_ent);
    cudaGetSymbolAddress((void**)&p_off_usr, g_off_usr);
    cudaGetSymbolAddress((void**)&p_packed,  g_packed);
    cudaGetSymbolAddress((void**)&p_items,   g_items);
    cudaGetSymbolAddress((void**)&p_entB,    g_entB);
    cudaGetSymbolAddress((void**)&p_usrB,    g_usrB);

    hist_both_k<<<2048, 256>>>(eidx, uidx, relw, latent);                    // #0
    scan_both_k<<<2, 1024>>>();                                              // #1
    scatter_both_k<<<2048, 256>>>(eidx, eidx + E_N, etype, uidx, iidx);      // #2

    float4* res_e = (float4*)out;
    float4* res_u = (float4*)(out + (size_t)N_ENT * DIM);

    // hop 0 (#3): base embeddings in; init residual; ZBLK tail blocks re-zero cnt
    fused_hop_k<<<EBLK + UBLK + ZBLK, 256>>>(
        (const float4*)entity_emb, (const float4*)user_emb, aggw, 0, 1,
        p_off_ent, p_packed, p_off_usr, p_items,
        (float4*)p_entB, (float4*)p_usrB, res_e, res_u);

    // hop 1 (#4): hop-0 outputs in; accumulate residual only
    fused_hop_k<<<EBLK + UBLK, 256>>>(
        (const float4*)p_entB, (const float4*)p_usrB, aggw, 1, 0,
        p_off_ent, p_packed, p_off_usr, p_items,
        nullptr, nullptr, res_e, res_u);
}

// round 14
// speedup vs baseline: 1.2437x; 1.0521x over previous
#include <cuda_runtime.h>
#include <math.h>

#define N_ENT 200000
#define N_USR 100000
#define DIM   64
#define E_N   1500000
#define NI_N  1000000
#define N_RELM1 10
#define WPB  8                             // warps per block
#define HPW  2                             // heads per warp (16 lanes each)
#define EBLK (N_ENT / (WPB * HPW))         // 12500 (exact)
#define UBLK (N_USR / (WPB * HPW))         // 6250  (exact)
#define ZBLK 512                           // cnt-rezero blocks appended to hop0 grid
#define BMAX 48                            // degree buckets for pair-balancing sort

// ---------------- device scratch (no allocation allowed) ----------------
// Invariant: g_cnt_* are all-zero at entry to kernel_launch (zero-init at load;
// hop0 tail blocks re-zero them after scatter each call). All bucket arrays are
// fully rewritten every call before use (scan writes boff+bcur, scatter fills perm).
__device__ int   g_remap[16];
__device__ int   g_cnt_ent[N_ENT];
__device__ int   g_off_ent[N_ENT + 1];
__device__ int   g_cnt_usr[N_USR];
__device__ int   g_off_usr[N_USR + 1];
__device__ int   g_packed[E_N];      // tail | (virt<<18)
__device__ int   g_items[NI_N];
__device__ int   g_boff_ent[BMAX];
__device__ int   g_bcur_ent[BMAX];
__device__ int   g_boff_usr[BMAX];
__device__ int   g_bcur_usr[BMAX];
__device__ int   g_perm_ent[N_ENT]; // head ids sorted by degree (pair-balanced)
__device__ int   g_perm_usr[N_USR];
__device__ float g_entB[N_ENT * DIM];
__device__ float g_usrB[N_USR * DIM];

// ---------------- helpers ----------------
__device__ __forceinline__ float wsum16(float v) {
    #pragma unroll
    for (int o = 8; o > 0; o >>= 1) v += __shfl_xor_sync(0xffffffffu, v, o);
    return v;
}
__device__ __forceinline__ float dot4(float4 a, float4 b) {
    return a.x * b.x + a.y * b.y + a.z * b.z + a.w * b.w;
}
__device__ __forceinline__ void add4(float4& A, float4 n) {
    A.x += n.x; A.y += n.y; A.z += n.z; A.w += n.w;
}
__device__ __forceinline__ void fma4(float4& A, float s, float4 n) {
    A.x += s * n.x; A.y += s * n.y; A.z += s * n.z; A.w += s * n.w;
}
// squash(A*inv) + base  (16-lane variant)
__device__ __forceinline__ float4 squash_addi4(float4 A, float inv, float4 base) {
    float4 u = make_float4(A.x * inv, A.y * inv, A.z * inv, A.w * inv);
    float sq = wsum16(dot4(u, u));
    float s = __fdividef(sq, (sq + 1.0f) * fmaxf(sqrtf(sq), 1e-12f));
    return make_float4(u.x * s + base.x, u.y * s + base.y,
                       u.z * s + base.z, u.w * s + base.w);
}

// ---------------- preprocessing (3 launches) ----------------

__global__ void __launch_bounds__(256)
hist_both_k(const int* __restrict__ heads, const int* __restrict__ uidx,
            const float* __restrict__ relw, const float* __restrict__ lat) {
    int gi = blockIdx.x * blockDim.x + threadIdx.x;
    if (gi < N_RELM1) {
        float best = -1e30f; int bi = 0;
        for (int v = 0; v < 3; v++) {
            float sdot = 0.f;
            #pragma unroll 1
            for (int k = 0; k < DIM; k++) sdot += relw[gi * DIM + k] * lat[v * DIM + k];
            if (sdot > best) { best = sdot; bi = v; }
        }
        g_remap[gi] = bi;
    }
    int total = E_N + NI_N;
    for (int i = gi; i < total; i += gridDim.x * blockDim.x) {
        if (i < E_N) atomicAdd(&g_cnt_ent[heads[i]], 1);
        else         atomicAdd(&g_cnt_usr[uidx[i - E_N]], 1);
    }
}

// exclusive scan + re-zero cnt + degree-bucket histogram -> bucket offsets/cursors
__global__ void __launch_bounds__(1024) scan_both_k() {
    int *cnt, *off; int n;
    if (blockIdx.x == 0) { cnt = g_cnt_ent; off = g_off_ent; n = N_ENT; }
    else                 { cnt = g_cnt_usr; off = g_off_usr; n = N_USR; }
    const int tid = threadIdx.x;
    const int lane = tid & 31, wid = tid >> 5;
    __shared__ int wsh[32];
    __shared__ int carry_s;
    __shared__ int sh_b[BMAX];
    if (tid == 0) carry_s = 0;
    if (tid < BMAX) sh_b[tid] = 0;
    __syncthreads();
    for (int base = 0; base < n; base += 1024) {
        int i = base + tid;
        int v = (i < n) ? cnt[i] : 0;
        if (i < n) atomicAdd(&sh_b[min(v, BMAX - 1)], 1);   // degree histogram
        int x = v;
        #pragma unroll
        for (int o = 1; o < 32; o <<= 1) {
            int t = __shfl_up_sync(0xffffffffu, x, o);
            if (lane >= o) x += t;
        }
        if (lane == 31) wsh[wid] = x;
        __syncthreads();
        if (wid == 0) {
            int y = wsh[lane];
            #pragma unroll
            for (int o = 1; o < 32; o <<= 1) {
                int t = __shfl_up_sync(0xffffffffu, y, o);
                if (lane >= o) y += t;
            }
            wsh[lane] = y;
        }
        __syncthreads();
        int warp_off = (wid > 0) ? wsh[wid - 1] : 0;
        int incl = x + warp_off;
        int carry = carry_s;
        if (i < n) { off[i] = carry + incl - v; cnt[i] = 0; }
        __syncthreads();
        if (tid == 1023) carry_s = carry + incl;
        __syncthreads();
    }
    if (tid == 0) {
        off[n] = carry_s;
        // bucket offsets + zero cursors (tiny serial scan over 48 bins)
        int* boff = (blockIdx.x == 0) ? g_boff_ent : g_boff_usr;
        int* bcur = (blockIdx.x == 0) ? g_bcur_ent : g_bcur_usr;
        int acc = 0;
        for (int b = 0; b < BMAX; b++) {
            boff[b] = acc; acc += sh_b[b]; bcur[b] = 0;
        }
    }
}

// scatter edges + user items into CSR; counting-sort node ids by degree into perm
__global__ void __launch_bounds__(256)
scatter_both_k(const int* __restrict__ heads, const int* __restrict__ tails,
               const int* __restrict__ et,
               const int* __restrict__ uidx, const int* __restrict__ iidx) {
    int total = E_N + NI_N + N_ENT + N_USR;
    for (int i = blockIdx.x * blockDim.x + threadIdx.x; i < total; i += gridDim.x * blockDim.x) {
        if (i < E_N) {
            int h = heads[i];
            int pos = g_off_ent[h] + atomicAdd(&g_cnt_ent[h], 1);
            int v = g_remap[et[i] - 1];
            g_packed[pos] = tails[i] | (v << 18);
        } else if (i < E_N + NI_N) {
            int k = i - E_N;
            int u = uidx[k];
            int pos = g_off_usr[u] + atomicAdd(&g_cnt_usr[u], 1);
            g_items[pos] = iidx[k];
        } else {
            int h = i - (E_N + NI_N);
            if (h < N_ENT) {
                int deg = g_off_ent[h + 1] - g_off_ent[h];
                int b = min(deg, BMAX - 1);
                int pos = g_boff_ent[b] + atomicAdd(&g_bcur_ent[b], 1);
                g_perm_ent[pos] = h;
            } else {
                h -= N_ENT;
                int deg = g_off_usr[h + 1] - g_off_usr[h];
                int b = min(deg, BMAX - 1);
                int pos = g_boff_usr[b] + atomicAdd(&g_bcur_usr[b], 1);
                g_perm_usr[pos] = h;
            }
        }
    }
}

// ---------------- fused hop kernel: 2 degree-matched heads per warp ----------------
__global__ void __launch_bounds__(256, 4)
fused_hop_k(const float4* __restrict__ ent_in, const float4* __restrict__ usr_in,
            const float* __restrict__ aggw, int hop, int init,
            const int* __restrict__ off_e, const int* __restrict__ packed,
            const int* __restrict__ off_u, const int* __restrict__ items,
            float4* __restrict__ ent_store, float4* __restrict__ usr_store,
            float4* __restrict__ res_ent, float4* __restrict__ res_usr)
{
    __shared__ float s_d[WPB][32];     // pass-1 dots: [warp][half*16 + j]

    const int wid  = threadIdx.x >> 5;
    const int lane = threadIdx.x & 31;
    const int l16  = lane & 15;
    const int half = lane >> 4;
    float* __restrict__ sd = &s_d[wid][half * 16];

    if (blockIdx.x >= EBLK + UBLK) {
        // cnt re-zero duty (hop0 only): restore the all-zero invariant
        int i = (blockIdx.x - (EBLK + UBLK)) * 256 + threadIdx.x;
        for (; i < N_ENT + N_USR; i += ZBLK * 256) {
            if (i < N_ENT) g_cnt_ent[i] = 0;
            else           g_cnt_usr[i - N_ENT] = 0;
        }
        return;
    }

    if (blockIdx.x < EBLK) {
        // ======================= ENTITY (2 degree-matched heads / warp) ========
        int slot = (blockIdx.x * WPB + wid) * HPW + half;
        int w = g_perm_ent[slot];                        // degree-sorted head id

        float4 en = ent_in[w * 16 + l16];
        int s = off_e[w], e = off_e[w + 1];
        int deg = e - s;
        int mdeg = max(deg, __shfl_xor_sync(0xffffffffu, deg, 16));  // ~= deg now

        float a0 = aggw[hop * 3 + 0], a1 = aggw[hop * 3 + 1], a2 = aggw[hop * 3 + 2];
        float mx = fmaxf(a0, fmaxf(a1, a2));
        float e0 = __expf(a0 - mx), e1 = __expf(a1 - mx), e2 = __expf(a2 - mx);
        float inv = __fdividef(1.0f, e0 + e1 + e2);
        float w0 = e0 * inv, w1 = e1 * inv, w2 = e2 * inv;

        float4 u30, u31, u32;

        if (mdeg <= 16) {
            // ---------- fast path: own half's edges resident in one register ----------
            int pk = (l16 < deg) ? packed[s + l16] : 0;

            // pass 0
            float4 A0 = {0,0,0,0}, A1 = {0,0,0,0}, A2 = {0,0,0,0};
            int c0 = 0, c1 = 0, c2 = 0;
            for (int j = 0; j < mdeg; j++) {
                int p = __shfl_sync(0xffffffffu, pk, j, 16);
                int t = p & 0x3FFFF, v = p >> 18;
                float4 nt = ent_in[t * 16 + l16];
                if (j < deg) {
                    if (v == 0)      { add4(A0, nt); c0++; }
                    else if (v == 1) { add4(A1, nt); c1++; }
                    else             { add4(A2, nt); c2++; }
                }
            }
            float i0 = __fdividef(1.f, fmaxf((float)c0, 1.f));
            float i1 = __fdividef(1.f, fmaxf((float)c1, 1.f));
            float i2 = __fdividef(1.f, fmaxf((float)c2, 1.f));
            float4 u10 = squash_addi4(A0, i0, en);
            float4 u11 = squash_addi4(A1, i1, en);
            float4 u12 = squash_addi4(A2, i2, en);

            // pass 1: dots cached in sd
            A0 = make_float4(0,0,0,0); A1 = make_float4(0,0,0,0); A2 = make_float4(0,0,0,0);
            for (int j = 0; j < mdeg; j++) {
                int p = __shfl_sync(0xffffffffu, pk, j, 16);
                int t = p & 0x3FFFF, v = p >> 18;
                float4 nt = ent_in[t * 16 + l16];
                float4 uv = (v == 0) ? u10 : ((v == 1) ? u11 : u12);
                float d = wsum16(dot4(uv, nt));
                if (j < deg) {
                    if (l16 == 0) sd[j] = d;
                    if (v == 0)      fma4(A0, d, nt);
                    else if (v == 1) fma4(A1, d, nt);
                    else             fma4(A2, d, nt);
                }
            }
            float4 u20 = squash_addi4(A0, i0, en);
            float4 u21 = squash_addi4(A1, i1, en);
            float4 u22 = squash_addi4(A2, i2, en);

            __syncwarp();

            // pass 2: scale = d1^2 * d2 (d1 from sd; u1x dead here)
            A0 = make_float4(0,0,0,0); A1 = make_float4(0,0,0,0); A2 = make_float4(0,0,0,0);
            for (int j = 0; j < mdeg; j++) {
                int p = __shfl_sync(0xffffffffu, pk, j, 16);
                int t = p & 0x3FFFF, v = p >> 18;
                float4 nt = ent_in[t * 16 + l16];
                float4 uB = (v == 0) ? u20 : ((v == 1) ? u21 : u22);
                float pb = wsum16(dot4(uB, nt));
                if (j < deg) {
                    float pa = sd[j];
                    float sc = pa * pa * pb;
                    if (v == 0)      fma4(A0, sc, nt);
                    else if (v == 1) fma4(A1, sc, nt);
                    else             fma4(A2, sc, nt);
                }
            }
            u30 = make_float4(A0.x * i0 + en.x, A0.y * i0 + en.y, A0.z * i0 + en.z, A0.w * i0 + en.w);
            u31 = make_float4(A1.x * i1 + en.x, A1.y * i1 + en.y, A1.z * i1 + en.z, A1.w * i1 + en.w);
            u32 = make_float4(A2.x * i2 + en.x, A2.y * i2 + en.y, A2.z * i2 + en.z, A2.w * i2 + en.w);
        } else {
            // ---------- generic path (rare mdeg > 16) ----------
            float4 A0 = {0,0,0,0}, A1 = {0,0,0,0}, A2 = {0,0,0,0};
            int c0 = 0, c1 = 0, c2 = 0;
            for (int b = 0; b < mdeg; b += 16) {
                int m = min(16, mdeg - b);
                int idx = b + l16;
                int pk = (idx < deg) ? packed[s + idx] : 0;
                for (int j = 0; j < m; j++) {
                    int p = __shfl_sync(0xffffffffu, pk, j, 16);
                    int t = p & 0x3FFFF, v = p >> 18;
                    float4 nt = ent_in[t * 16 + l16];
                    if (b + j < deg) {
                        if (v == 0)      { add4(A0, nt); c0++; }
                        else if (v == 1) { add4(A1, nt); c1++; }
                        else             { add4(A2, nt); c2++; }
                    }
                }
            }
            float i0 = __fdividef(1.f, fmaxf((float)c0, 1.f));
            float i1 = __fdividef(1.f, fmaxf((float)c1, 1.f));
            float i2 = __fdividef(1.f, fmaxf((float)c2, 1.f));
            float4 u10 = squash_addi4(A0, i0, en);
            float4 u11 = squash_addi4(A1, i1, en);
            float4 u12 = squash_addi4(A2, i2, en);

            A0 = make_float4(0,0,0,0); A1 = make_float4(0,0,0,0); A2 = make_float4(0,0,0,0);
            for (int b = 0; b < mdeg; b += 16) {
                int m = min(16, mdeg - b);
                int idx = b + l16;
                int pk = (idx < deg) ? packed[s + idx] : 0;
                for (int j = 0; j < m; j++) {
                    int p = __shfl_sync(0xffffffffu, pk, j, 16);
                    int t = p & 0x3FFFF, v = p >> 18;
                    float4 nt = ent_in[t * 16 + l16];
                    float4 uv = (v == 0) ? u10 : ((v == 1) ? u11 : u12);
                    float d = wsum16(dot4(uv, nt));
                    if (b + j < deg) {
                        if (v == 0)      fma4(A0, d, nt);
                        else if (v == 1) fma4(A1, d, nt);
                        else             fma4(A2, d, nt);
                    }
                }
            }
            float4 u20 = squash_addi4(A0, i0, en);
            float4 u21 = squash_addi4(A1, i1, en);
            float4 u22 = squash_addi4(A2, i2, en);

            A0 = make_float4(0,0,0,0); A1 = make_float4(0,0,0,0); A2 = make_float4(0,0,0,0);
            for (int b = 0; b < mdeg; b += 16) {
                int m = min(16, mdeg - b);
                int idx = b + l16;
                int pk = (idx < deg) ? packed[s + idx] : 0;
                for (int j = 0; j < m; j++) {
                    int p = __shfl_sync(0xffffffffu, pk, j, 16);
                    int t = p & 0x3FFFF, v = p >> 18;
                    float4 nt = ent_in[t * 16 + l16];
                    float4 uA = (v == 0) ? u10 : ((v == 1) ? u11 : u12);
                    float4 uB = (v == 0) ? u20 : ((v == 1) ? u21 : u22);
                    float pa = dot4(uA, nt);
                    float pb = dot4(uB, nt);
                    #pragma unroll
                    for (int o = 8; o > 0; o >>= 1) {
                        pa += __shfl_xor_sync(0xffffffffu, pa, o);
                        pb += __shfl_xor_sync(0xffffffffu, pb, o);
                    }
                    if (b + j < deg) {
                        float sc = pa * pa * pb;
                        if (v == 0)      fma4(A0, sc, nt);
                        else if (v == 1) fma4(A1, sc, nt);
                        else             fma4(A2, sc, nt);
                    }
                }
            }
            u30 = make_float4(A0.x * i0 + en.x, A0.y * i0 + en.y, A0.z * i0 + en.z, A0.w * i0 + en.w);
            u31 = make_float4(A1.x * i1 + en.x, A1.y * i1 + en.y, A1.z * i1 + en.z, A1.w * i1 + en.w);
            u32 = make_float4(A2.x * i2 + en.x, A2.y * i2 + en.y, A2.z * i2 + en.z, A2.w * i2 + en.w);
        }

        // weighted agg + l2norm + residual
        float4 ag = make_float4(w0 * u30.x + w1 * u31.x + w2 * u32.x,
                                w0 * u30.y + w1 * u31.y + w2 * u32.y,
                                w0 * u30.z + w1 * u31.z + w2 * u32.z,
                                w0 * u30.w + w1 * u31.w + w2 * u32.w);
        float sq = wsum16(dot4(ag, ag));
        float in2 = __fdividef(1.0f, fmaxf(sqrtf(sq), 1e-12f));
        float4 o = make_float4(ag.x * in2, ag.y * in2, ag.z * in2, ag.w * in2);
        if (ent_store) ent_store[w * 16 + l16] = o;
        float4 r;
        if (init) r = make_float4(en.x + o.x, en.y + o.y, en.z + o.z, en.w + o.w);
        else {
            r = res_ent[w * 16 + l16];
            r.x += o.x; r.y += o.y; r.z += o.z; r.w += o.w;
        }
        res_ent[w * 16 + l16] = r;

    } else {
        // ======================= USER (2 degree-matched users / warp) ==========
        int slot = ((blockIdx.x - EBLK) * WPB + wid) * HPW + half;
        int w = g_perm_usr[slot];                        // degree-sorted user id

        float4 un = usr_in[w * 16 + l16];
        int s = off_u[w], e = off_u[w + 1];
        int deg = e - s;
        int mdeg = max(deg, __shfl_xor_sync(0xffffffffu, deg, 16));
        float invd = __fdividef(1.f, fmaxf((float)deg, 1.f));
        float4 u3;

        if (mdeg <= 16) {
            // ---------- fast path ----------
            int it = (l16 < deg) ? items[s + l16] : 0;

            float4 A = {0,0,0,0};
            for (int j = 0; j < mdeg; j++) {
                int t = __shfl_sync(0xffffffffu, it, j, 16);
                float4 nt = ent_in[t * 16 + l16];
                if (j < deg) add4(A, nt);
            }
            float4 u1 = squash_addi4(A, invd, un);

            A = make_float4(0,0,0,0);
            for (int j = 0; j < mdeg; j++) {
                int t = __shfl_sync(0xffffffffu, it, j, 16);
                float4 nt = ent_in[t * 16 + l16];
                float d = wsum16(dot4(u1, nt));
                if (j < deg) fma4(A, d, nt);
            }
            float4 u2 = squash_addi4(A, invd, un);

            A = make_float4(0,0,0,0);
            for (int j = 0; j < mdeg; j++) {
                int t = __shfl_sync(0xffffffffu, it, j, 16);
                float4 nt = ent_in[t * 16 + l16];
                float d = wsum16(dot4(u2, nt));
                if (j < deg) fma4(A, d, nt);
            }
            u3 = make_float4(A.x * invd + un.x, A.y * invd + un.y,
                             A.z * invd + un.z, A.w * invd + un.w);
        } else {
            // ---------- generic path ----------
            float4 A = {0,0,0,0};
            for (int b = 0; b < mdeg; b += 16) {
                int m = min(16, mdeg - b);
                int idx = b + l16;
                int it = (idx < deg) ? items[s + idx] : 0;
                for (int j = 0; j < m; j++) {
                    int t = __shfl_sync(0xffffffffu, it, j, 16);
                    float4 nt = ent_in[t * 16 + l16];
                    if (b + j < deg) add4(A, nt);
                }
            }
            float4 u1 = squash_addi4(A, invd, un);

            A = make_float4(0,0,0,0);
            for (int b = 0; b < mdeg; b += 16) {
                int m = min(16, mdeg - b);
                int idx = b + l16;
                int it = (idx < deg) ? items[s + idx] : 0;
                for (int j = 0; j < m; j++) {
                    int t = __shfl_sync(0xffffffffu, it, j, 16);
                    float4 nt = ent_in[t * 16 + l16];
                    float d = wsum16(dot4(u1, nt));
                    if (b + j < deg) fma4(A, d, nt);
                }
            }
            float4 u2 = squash_addi4(A, invd, un);

            A = make_float4(0,0,0,0);
            for (int b = 0; b < mdeg; b += 16) {
                int m = min(16, mdeg - b);
                int idx = b + l16;
                int it = (idx < deg) ? items[s + idx] : 0;
                for (int j = 0; j < m; j++) {
                    int t = __shfl_sync(0xffffffffu, it, j, 16);
                    float4 nt = ent_in[t * 16 + l16];
                    float d = wsum16(dot4(u2, nt));
                    if (b + j < deg) fma4(A, d, nt);
                }
            }
            u3 = make_float4(A.x * invd + un.x, A.y * invd + un.y,
                             A.z * invd + un.z, A.w * invd + un.w);
        }

        float sq = wsum16(dot4(u3, u3));
        float in2 = __fdividef(1.0f, fmaxf(sqrtf(sq), 1e-12f));
        float4 o = make_float4(u3.x * in2, u3.y * in2, u3.z * in2, u3.w * in2);
        if (usr_store) usr_store[w * 16 + l16] = o;
        float4 r;
        if (init) r = make_float4(un.x + o.x, un.y + o.y, un.z + o.z, un.w + o.w);
        else {
            r = res_usr[w * 16 + l16];
            r.x += o.x; r.y += o.y; r.z += o.z; r.w += o.w;
        }
        res_usr[w * 16 + l16] = r;
    }
}

// ---------------- launch (5 launches) ----------------
extern "C" void kernel_launch(void* const* d_in, const int* in_sizes, int n_in,
                              void* d_out, int out_size) {
    const float* entity_emb = (const float*)d_in[0];
    const float* user_emb   = (const float*)d_in[1];
    const float* latent     = (const float*)d_in[2];
    const float* relw       = (const float*)d_in[3];
    const float* aggw       = (const float*)d_in[4];
    const int*   eidx       = (const int*)d_in[5];   // [2,E]: head row, then tail row
    const int*   etype      = (const int*)d_in[6];
    const int*   uidx       = (const int*)d_in[7];
    const int*   iidx       = (const int*)d_in[8];
    float* out = (float*)d_out;

    int *p_off_ent, *p_off_usr, *p_packed, *p_items;
    float *p_entB, *p_usrB;
    cudaGetSymbolAddress((void**)&p_off_ent, g_off_ent);
    cudaGetSymbolAddress((void**)&p_off_usr, g_off_usr);
    cudaGetSymbolAddress((void**)&p_packed,  g_packed);
    cudaGetSymbolAddress((void**)&p_items,   g_items);
    cudaGetSymbolAddress((void**)&p_entB,    g_entB);
    cudaGetSymbolAddress((void**)&p_usrB,    g_usrB);

    hist_both_k<<<2048, 256>>>(eidx, uidx, relw, latent);                    // #0
    scan_both_k<<<2, 1024>>>();                                              // #1
    scatter_both_k<<<2048, 256>>>(eidx, eidx + E_N, etype, uidx, iidx);      // #2

    float4* res_e = (float4*)out;
    float4* res_u = (float4*)(out + (size_t)N_ENT * DIM);

    // hop 0 (#3): base embeddings in; init residual; ZBLK tail blocks re-zero cnt
    fused_hop_k<<<EBLK + UBLK + ZBLK, 256>>>(
        (const float4*)entity_emb, (const float4*)user_emb, aggw, 0, 1,
        p_off_ent, p_packed, p_off_usr, p_items,
        (float4*)p_entB, (float4*)p_usrB, res_e, res_u);

    // hop 1 (#4): hop-0 outputs in; accumulate residual only
    fused_hop_k<<<EBLK + UBLK, 256>>>(
        (const float4*)p_entB, (const float4*)p_usrB, aggw, 1, 0,
        p_off_ent, p_packed, p_off_usr, p_items,
        nullptr, nullptr, res_e, res_u);
}

// round 15
// speedup vs baseline: 1.4886x; 1.1970x over previous
#include <cuda_runtime.h>
#include <math.h>

#define N_ENT 200000
#define N_USR 100000
#define DIM   64
#define E_N   1500000
#define NI_N  1000000
#define N_RELM1 10
#define WPB  8                             // warps per block
#define HPW  2                             // heads per warp (16 lanes each)
#define EBLK (N_ENT / (WPB * HPW))         // 12500 (exact)
#define UBLK (N_USR / (WPB * HPW))         // 6250  (exact)
#define ZBLK 512                           // cnt-rezero blocks appended to hop0 grid
#define BMAX 48                            // degree buckets for pair-balancing sort
#define TILE 4096                          // scan tile (1024 thr x 4)
#define TILES_E ((N_ENT + TILE - 1) / TILE)   // 49
#define TILES_U ((N_USR + TILE - 1) / TILE)   // 25

// ---------------- device scratch (no allocation allowed) ----------------
// Invariant: g_cnt_* are all-zero at entry to kernel_launch (zero-init at load;
// hop0 tail blocks re-zero them after scatter each call). Chain/bucket state is
// re-zeroed by hist_both_k each call before use (stream-ordered).
__device__ int   g_remap[16];
__device__ int   g_cnt_ent[N_ENT];
__device__ int   g_off_ent[N_ENT + 1];
__device__ int   g_cnt_usr[N_USR];
__device__ int   g_off_usr[N_USR + 1];
__device__ int   g_packed[E_N];      // tail | (virt<<18)
__device__ int   g_items[NI_N];
__device__ unsigned long long g_pref_ent[TILES_E];
__device__ unsigned long long g_pref_usr[TILES_U];
__device__ int   g_bkt_ent[BMAX];
__device__ int   g_bkt_usr[BMAX];
__device__ int   g_done_ent, g_done_usr;
__device__ int   g_boff_ent[BMAX];
__device__ int   g_bcur_ent[BMAX];
__device__ int   g_boff_usr[BMAX];
__device__ int   g_bcur_usr[BMAX];
__device__ int   g_perm_ent[N_ENT]; // head ids sorted by degree (pair-balanced)
__device__ int   g_perm_usr[N_USR];
__device__ float g_entB[N_ENT * DIM];
__device__ float g_usrB[N_USR * DIM];

// ---------------- helpers ----------------
__device__ __forceinline__ float wsum16(float v) {
    #pragma unroll
    for (int o = 8; o > 0; o >>= 1) v += __shfl_xor_sync(0xffffffffu, v, o);
    return v;
}
__device__ __forceinline__ float dot4(float4 a, float4 b) {
    return a.x * b.x + a.y * b.y + a.z * b.z + a.w * b.w;
}
__device__ __forceinline__ void add4(float4& A, float4 n) {
    A.x += n.x; A.y += n.y; A.z += n.z; A.w += n.w;
}
__device__ __forceinline__ void fma4(float4& A, float s, float4 n) {
    A.x += s * n.x; A.y += s * n.y; A.z += s * n.z; A.w += s * n.w;
}
__device__ __forceinline__ float4 squash_addi4(float4 A, float inv, float4 base) {
    float4 u = make_float4(A.x * inv, A.y * inv, A.z * inv, A.w * inv);
    float sq = wsum16(dot4(u, u));
    float s = __fdividef(sq, (sq + 1.0f) * fmaxf(sqrtf(sq), 1e-12f));
    return make_float4(u.x * s + base.x, u.y * s + base.y,
                       u.z * s + base.z, u.w * s + base.w);
}

// ---------------- preprocessing (3 launches) ----------------

// L0: degree histograms + remap + zero chain/bucket state for this call
__global__ void __launch_bounds__(256)
hist_both_k(const int* __restrict__ heads, const int* __restrict__ uidx,
            const float* __restrict__ relw, const float* __restrict__ lat) {
    int gi = blockIdx.x * blockDim.x + threadIdx.x;
    if (gi < N_RELM1) {
        float best = -1e30f; int bi = 0;
        for (int v = 0; v < 3; v++) {
            float sdot = 0.f;
            #pragma unroll 1
            for (int k = 0; k < DIM; k++) sdot += relw[gi * DIM + k] * lat[v * DIM + k];
            if (sdot > best) { best = sdot; bi = v; }
        }
        g_remap[gi] = bi;
    }
    if (gi < TILES_E) g_pref_ent[gi] = 0ULL;
    if (gi < TILES_U) g_pref_usr[gi] = 0ULL;
    if (gi < BMAX) { g_bkt_ent[gi] = 0; g_bkt_usr[gi] = 0; }
    if (gi == 0) { g_done_ent = 0; g_done_usr = 0; }
    int total = E_N + NI_N;
    for (int i = gi; i < total; i += gridDim.x * blockDim.x) {
        if (i < E_N) atomicAdd(&g_cnt_ent[heads[i]], 1);
        else         atomicAdd(&g_cnt_usr[uidx[i - E_N]], 1);
    }
}

// L1: 74-block chained scan: exclusive CSR offsets + re-zero cnt + degree-bucket
// histogram; the last-done block of each array computes bucket offsets/cursors.
__global__ void __launch_bounds__(1024) scan_chain_k() {
    bool isEnt = blockIdx.x < TILES_E;
    int tile    = isEnt ? blockIdx.x : blockIdx.x - TILES_E;
    int n       = isEnt ? N_ENT : N_USR;
    int ntiles  = isEnt ? TILES_E : TILES_U;
    int* cnt    = isEnt ? g_cnt_ent : g_cnt_usr;
    int* off    = isEnt ? g_off_ent : g_off_usr;
    unsigned long long* pref = isEnt ? g_pref_ent : g_pref_usr;
    int* bkt    = isEnt ? g_bkt_ent : g_bkt_usr;

    const int tid = threadIdx.x, lane = tid & 31, wid = tid >> 5;
    __shared__ int wsh[32];
    __shared__ unsigned long long sprev;
    __shared__ int shb[BMAX];
    __shared__ int sb2[BMAX];
    __shared__ int slast;
    if (tid < BMAX) shb[tid] = 0;
    __syncthreads();

    int i0 = tile * TILE + tid * 4;
    int a0 = 0, a1 = 0, a2 = 0, a3 = 0;
    if (i0 < n)     a0 = cnt[i0];
    if (i0 + 1 < n) a1 = cnt[i0 + 1];
    if (i0 + 2 < n) a2 = cnt[i0 + 2];
    if (i0 + 3 < n) a3 = cnt[i0 + 3];
    if (i0 < n)     atomicAdd(&shb[min(a0, BMAX - 1)], 1);
    if (i0 + 1 < n) atomicAdd(&shb[min(a1, BMAX - 1)], 1);
    if (i0 + 2 < n) atomicAdd(&shb[min(a2, BMAX - 1)], 1);
    if (i0 + 3 < n) atomicAdd(&shb[min(a3, BMAX - 1)], 1);

    int tsum = a0 + a1 + a2 + a3;
    int x = tsum;
    #pragma unroll
    for (int o = 1; o < 32; o <<= 1) {
        int t = __shfl_up_sync(0xffffffffu, x, o);
        if (lane >= o) x += t;
    }
    if (lane == 31) wsh[wid] = x;
    __syncthreads();
    if (wid == 0) {
        int y = wsh[lane];
        #pragma unroll
        for (int o = 1; o < 32; o <<= 1) {
            int t = __shfl_up_sync(0xffffffffu, y, o);
            if (lane >= o) y += t;
        }
        wsh[lane] = y;
    }
    __syncthreads();
    int blockTotal = wsh[31];
    int warpoff = (wid > 0) ? wsh[wid - 1] : 0;
    int incl = x + warpoff;

    // chained prefix: wait for predecessor, publish own inclusive prefix
    if (tid == 0) {
        unsigned long long p = 0ULL;
        if (tile > 0) {
            while (((p = atomicAdd(&pref[tile - 1], 0ULL)) >> 63) == 0ULL) {}
            p &= 0x7FFFFFFFFFFFFFFFULL;
        }
        sprev = p;
        atomicExch(&pref[tile], (1ULL << 63) | (p + (unsigned long long)blockTotal));
        if (tile == ntiles - 1) off[n] = (int)(p + (unsigned long long)blockTotal);
    }
    __syncthreads();
    int carry = (int)sprev;
    int ex = carry + incl - tsum;
    if (i0 < n)     { off[i0]     = ex;                 cnt[i0]     = 0; }
    if (i0 + 1 < n) { off[i0 + 1] = ex + a0;            cnt[i0 + 1] = 0; }
    if (i0 + 2 < n) { off[i0 + 2] = ex + a0 + a1;       cnt[i0 + 2] = 0; }
    if (i0 + 3 < n) { off[i0 + 3] = ex + a0 + a1 + a2;  cnt[i0 + 3] = 0; }

    // bucket histogram to global; last-done block computes boff/bcur
    if (tid < BMAX && shb[tid]) atomicAdd(&bkt[tid], shb[tid]);
    if (tid == 0) {
        __threadfence();
        int done = atomicAdd(isEnt ? &g_done_ent : &g_done_usr, 1);
        slast = (done == ntiles - 1);
    }
    __syncthreads();
    if (slast) {
        if (tid < BMAX) sb2[tid] = atomicAdd(&bkt[tid], 0);
        __syncthreads();
        if (tid == 0) {
            int* boff = isEnt ? g_boff_ent : g_boff_usr;
            int* bcur = isEnt ? g_bcur_ent : g_bcur_usr;
            int acc = 0;
            for (int b = 0; b < BMAX; b++) { boff[b] = acc; acc += sb2[b]; bcur[b] = 0; }
        }
    }
}

// L2: scatter edges + user items into CSR; warp-aggregated counting-sort of node
// ids by degree into perm.
__global__ void __launch_bounds__(256)
scatter_both_k(const int* __restrict__ heads, const int* __restrict__ tails,
               const int* __restrict__ et,
               const int* __restrict__ uidx, const int* __restrict__ iidx) {
    int total = E_N + NI_N + N_ENT + N_USR;
    for (int i = blockIdx.x * blockDim.x + threadIdx.x; i < total; i += gridDim.x * blockDim.x) {
        if (i < E_N) {
            int h = heads[i];
            int pos = g_off_ent[h] + atomicAdd(&g_cnt_ent[h], 1);
            int v = g_remap[et[i] - 1];
            g_packed[pos] = tails[i] | (v << 18);
        } else if (i < E_N + NI_N) {
            int k = i - E_N;
            int u = uidx[k];
            int pos = g_off_usr[u] + atomicAdd(&g_cnt_usr[u], 1);
            g_items[pos] = iidx[k];
        } else {
            int h = i - (E_N + NI_N);
            bool ent = (h < N_ENT);
            if (!ent) h -= N_ENT;
            int deg = ent ? (g_off_ent[h + 1] - g_off_ent[h])
                          : (g_off_usr[h + 1] - g_off_usr[h]);
            int b = min(deg, BMAX - 1);
            int key = b | (ent ? 64 : 0);
            unsigned am = __activemask();
            unsigned mk = __match_any_sync(am, key);
            int lanei = threadIdx.x & 31;
            int leader = __ffs(mk) - 1;
            int rank = __popc(mk & ((1u << lanei) - 1));
            int base = 0;
            if (lanei == leader)
                base = atomicAdd(ent ? &g_bcur_ent[b] : &g_bcur_usr[b], __popc(mk));
            base = __shfl_sync(mk, base, leader);
            int pos = (ent ? g_boff_ent : g_boff_usr)[b] + base + rank;
            if (ent) g_perm_ent[pos] = h; else g_perm_usr[pos] = h;
        }
    }
}

// ---------------- fused hop kernel: 2 degree-matched heads per warp ----------------
__global__ void __launch_bounds__(256, 4)
fused_hop_k(const float4* __restrict__ ent_in, const float4* __restrict__ usr_in,
            const float* __restrict__ aggw, int hop, int init,
            const int* __restrict__ off_e, const int* __restrict__ packed,
            const int* __restrict__ off_u, const int* __restrict__ items,
            float4* __restrict__ ent_store, float4* __restrict__ usr_store,
            float4* __restrict__ res_ent, float4* __restrict__ res_usr)
{
    __shared__ float s_d[WPB][32];     // pass-1 dots: [warp][half*16 + j]

    const int wid  = threadIdx.x >> 5;
    const int lane = threadIdx.x & 31;
    const int l16  = lane & 15;
    const int half = lane >> 4;
    float* __restrict__ sd = &s_d[wid][half * 16];

    if (blockIdx.x >= EBLK + UBLK) {
        // cnt re-zero duty (hop0 only): restore the all-zero invariant
        int i = (blockIdx.x - (EBLK + UBLK)) * 256 + threadIdx.x;
        for (; i < N_ENT + N_USR; i += ZBLK * 256) {
            if (i < N_ENT) g_cnt_ent[i] = 0;
            else           g_cnt_usr[i - N_ENT] = 0;
        }
        return;
    }

    if (blockIdx.x < EBLK) {
        // ======================= ENTITY (2 degree-matched heads / warp) ========
        int slot = (blockIdx.x * WPB + wid) * HPW + half;
        int w = g_perm_ent[slot];                        // degree-sorted head id

        float4 en = ent_in[w * 16 + l16];
        int s = off_e[w], e = off_e[w + 1];
        int deg = e - s;
        int mdeg = max(deg, __shfl_xor_sync(0xffffffffu, deg, 16));  // ~= deg now

        float a0 = aggw[hop * 3 + 0], a1 = aggw[hop * 3 + 1], a2 = aggw[hop * 3 + 2];
        float mx = fmaxf(a0, fmaxf(a1, a2));
        float e0 = __expf(a0 - mx), e1 = __expf(a1 - mx), e2 = __expf(a2 - mx);
        float inv = __fdividef(1.0f, e0 + e1 + e2);
        float w0 = e0 * inv, w1 = e1 * inv, w2 = e2 * inv;

        float4 u30, u31, u32;

        if (mdeg <= 16) {
            // ---------- fast path: own half's edges resident in one register ----------
            int pk = (l16 < deg) ? packed[s + l16] : 0;

            // pass 0
            float4 A0 = {0,0,0,0}, A1 = {0,0,0,0}, A2 = {0,0,0,0};
            int c0 = 0, c1 = 0, c2 = 0;
            for (int j = 0; j < mdeg; j++) {
                int p = __shfl_sync(0xffffffffu, pk, j, 16);
                int t = p & 0x3FFFF, v = p >> 18;
                float4 nt = ent_in[t * 16 + l16];
                if (j < deg) {
                    if (v == 0)      { add4(A0, nt); c0++; }
                    else if (v == 1) { add4(A1, nt); c1++; }
                    else             { add4(A2, nt); c2++; }
                }
            }
            float i0 = __fdividef(1.f, fmaxf((float)c0, 1.f));
            float i1 = __fdividef(1.f, fmaxf((float)c1, 1.f));
            float i2 = __fdividef(1.f, fmaxf((float)c2, 1.f));
            float4 u10 = squash_addi4(A0, i0, en);
            float4 u11 = squash_addi4(A1, i1, en);
            float4 u12 = squash_addi4(A2, i2, en);

            // pass 1: dots cached in sd
            A0 = make_float4(0,0,0,0); A1 = make_float4(0,0,0,0); A2 = make_float4(0,0,0,0);
            for (int j = 0; j < mdeg; j++) {
                int p = __shfl_sync(0xffffffffu, pk, j, 16);
                int t = p & 0x3FFFF, v = p >> 18;
                float4 nt = ent_in[t * 16 + l16];
                float4 uv = (v == 0) ? u10 : ((v == 1) ? u11 : u12);
                float d = wsum16(dot4(uv, nt));
                if (j < deg) {
                    if (l16 == 0) sd[j] = d;
                    if (v == 0)      fma4(A0, d, nt);
                    else if (v == 1) fma4(A1, d, nt);
                    else             fma4(A2, d, nt);
                }
            }
            float4 u20 = squash_addi4(A0, i0, en);
            float4 u21 = squash_addi4(A1, i1, en);
            float4 u22 = squash_addi4(A2, i2, en);

            __syncwarp();

            // pass 2: scale = d1^2 * d2 (d1 from sd; u1x dead here)
            A0 = make_float4(0,0,0,0); A1 = make_float4(0,0,0,0); A2 = make_float4(0,0,0,0);
            for (int j = 0; j < mdeg; j++) {
                int p = __shfl_sync(0xffffffffu, pk, j, 16);
                int t = p & 0x3FFFF, v = p >> 18;
                float4 nt = ent_in[t * 16 + l16];
                float4 uB = (v == 0) ? u20 : ((v == 1) ? u21 : u22);
                float pb = wsum16(dot4(uB, nt));
                if (j < deg) {
                    float pa = sd[j];
                    float sc = pa * pa * pb;
                    if (v == 0)      fma4(A0, sc, nt);
                    else if (v == 1) fma4(A1, sc, nt);
                    else             fma4(A2, sc, nt);
                }
            }
            u30 = make_float4(A0.x * i0 + en.x, A0.y * i0 + en.y, A0.z * i0 + en.z, A0.w * i0 + en.w);
            u31 = make_float4(A1.x * i1 + en.x, A1.y * i1 + en.y, A1.z * i1 + en.z, A1.w * i1 + en.w);
            u32 = make_float4(A2.x * i2 + en.x, A2.y * i2 + en.y, A2.z * i2 + en.z, A2.w * i2 + en.w);
        } else {
            // ---------- generic path (rare mdeg > 16) ----------
            float4 A0 = {0,0,0,0}, A1 = {0,0,0,0}, A2 = {0,0,0,0};
            int c0 = 0, c1 = 0, c2 = 0;
            for (int b = 0; b < mdeg; b += 16) {
                int m = min(16, mdeg - b);
                int idx = b + l16;
                int pk = (idx < deg) ? packed[s + idx] : 0;
                for (int j = 0; j < m; j++) {
                    int p = __shfl_sync(0xffffffffu, pk, j, 16);
                    int t = p & 0x3FFFF, v = p >> 18;
                    float4 nt = ent_in[t * 16 + l16];
                    if (b + j < deg) {
                        if (v == 0)      { add4(A0, nt); c0++; }
                        else if (v == 1) { add4(A1, nt); c1++; }
                        else             { add4(A2, nt); c2++; }
                    }
                }
            }
            float i0 = __fdividef(1.f, fmaxf((float)c0, 1.f));
            float i1 = __fdividef(1.f, fmaxf((float)c1, 1.f));
            float i2 = __fdividef(1.f, fmaxf((float)c2, 1.f));
            float4 u10 = squash_addi4(A0, i0, en);
            float4 u11 = squash_addi4(A1, i1, en);
            float4 u12 = squash_addi4(A2, i2, en);

            A0 = make_float4(0,0,0,0); A1 = make_float4(0,0,0,0); A2 = make_float4(0,0,0,0);
            for (int b = 0; b < mdeg; b += 16) {
                int m = min(16, mdeg - b);
                int idx = b + l16;
                int pk = (idx < deg) ? packed[s + idx] : 0;
                for (int j = 0; j < m; j++) {
                    int p = __shfl_sync(0xffffffffu, pk, j, 16);
                    int t = p & 0x3FFFF, v = p >> 18;
                    float4 nt = ent_in[t * 16 + l16];
                    float4 uv = (v == 0) ? u10 : ((v == 1) ? u11 : u12);
                    float d = wsum16(dot4(uv, nt));
                    if (b + j < deg) {
                        if (v == 0)      fma4(A0, d, nt);
                        else if (v == 1) fma4(A1, d, nt);
                        else             fma4(A2, d, nt);
                    }
                }
            }
            float4 u20 = squash_addi4(A0, i0, en);
            float4 u21 = squash_addi4(A1, i1, en);
            float4 u22 = squash_addi4(A2, i2, en);

            A0 = make_float4(0,0,0,0); A1 = make_float4(0,0,0,0); A2 = make_float4(0,0,0,0);
            for (int b = 0; b < mdeg; b += 16) {
                int m = min(16, mdeg - b);
                int idx = b + l16;
                int pk = (idx < deg) ? packed[s + idx] : 0;
                for (int j = 0; j < m; j++) {
                    int p = __shfl_sync(0xffffffffu, pk, j, 16);
                    int t = p & 0x3FFFF, v = p >> 18;
                    float4 nt = ent_in[t * 16 + l16];
                    float4 uA = (v == 0) ? u10 : ((v == 1) ? u11 : u12);
                    float4 uB = (v == 0) ? u20 : ((v == 1) ? u21 : u22);
                    float pa = dot4(uA, nt);
                    float pb = dot4(uB, nt);
                    #pragma unroll
                    for (int o = 8; o > 0; o >>= 1) {
                        pa += __shfl_xor_sync(0xffffffffu, pa, o);
                        pb += __shfl_xor_sync(0xffffffffu, pb, o);
                    }
                    if (b + j < deg) {
                        float sc = pa * pa * pb;
                        if (v == 0)      fma4(A0, sc, nt);
                        else if (v == 1) fma4(A1, sc, nt);
                        else             fma4(A2, sc, nt);
                    }
                }
            }
            u30 = make_float4(A0.x * i0 + en.x, A0.y * i0 + en.y, A0.z * i0 + en.z, A0.w * i0 + en.w);
            u31 = make_float4(A1.x * i1 + en.x, A1.y * i1 + en.y, A1.z * i1 + en.z, A1.w * i1 + en.w);
            u32 = make_float4(A2.x * i2 + en.x, A2.y * i2 + en.y, A2.z * i2 + en.z, A2.w * i2 + en.w);
        }

        // weighted agg + l2norm + residual
        float4 ag = make_float4(w0 * u30.x + w1 * u31.x + w2 * u32.x,
                                w0 * u30.y + w1 * u31.y + w2 * u32.y,
                                w0 * u30.z + w1 * u31.z + w2 * u32.z,
                                w0 * u30.w + w1 * u31.w + w2 * u32.w);
        float sq = wsum16(dot4(ag, ag));
        float in2 = __fdividef(1.0f, fmaxf(sqrtf(sq), 1e-12f));
        float4 o = make_float4(ag.x * in2, ag.y * in2, ag.z * in2, ag.w * in2);
        if (ent_store) ent_store[w * 16 + l16] = o;
        float4 r;
        if (init) r = make_float4(en.x + o.x, en.y + o.y, en.z + o.z, en.w + o.w);
        else {
            r = res_ent[w * 16 + l16];
            r.x += o.x; r.y += o.y; r.z += o.z; r.w += o.w;
        }
        res_ent[w * 16 + l16] = r;

    } else {
        // ======================= USER (2 degree-matched users / warp) ==========
        int slot = ((blockIdx.x - EBLK) * WPB + wid) * HPW + half;
        int w = g_perm_usr[slot];                        // degree-sorted user id

        float4 un = usr_in[w * 16 + l16];
        int s = off_u[w], e = off_u[w + 1];
        int deg = e - s;
        int mdeg = max(deg, __shfl_xor_sync(0xffffffffu, deg, 16));
        float invd = __fdividef(1.f, fmaxf((float)deg, 1.f));
        float4 u3;

        if (mdeg <= 16) {
            // ---------- fast path ----------
            int it = (l16 < deg) ? items[s + l16] : 0;

            float4 A = {0,0,0,0};
            for (int j = 0; j < mdeg; j++) {
                int t = __shfl_sync(0xffffffffu, it, j, 16);
                float4 nt = ent_in[t * 16 + l16];
                if (j < deg) add4(A, nt);
            }
            float4 u1 = squash_addi4(A, invd, un);

            A = make_float4(0,0,0,0);
            for (int j = 0; j < mdeg; j++) {
                int t = __shfl_sync(0xffffffffu, it, j, 16);
                float4 nt = ent_in[t * 16 + l16];
                float d = wsum16(dot4(u1, nt));
                if (j < deg) fma4(A, d, nt);
            }
            float4 u2 = squash_addi4(A, invd, un);

            A = make_float4(0,0,0,0);
            for (int j = 0; j < mdeg; j++) {
                int t = __shfl_sync(0xffffffffu, it, j, 16);
                float4 nt = ent_in[t * 16 + l16];
                float d = wsum16(dot4(u2, nt));
                if (j < deg) fma4(A, d, nt);
            }
            u3 = make_float4(A.x * invd + un.x, A.y * invd + un.y,
                             A.z * invd + un.z, A.w * invd + un.w);
        } else {
            // ---------- generic path ----------
            float4 A = {0,0,0,0};
            for (int b = 0; b < mdeg; b += 16) {
                int m = min(16, mdeg - b);
                int idx = b + l16;
                int it = (idx < deg) ? items[s + idx] : 0;
                for (int j = 0; j < m; j++) {
                    int t = __shfl_sync(0xffffffffu, it, j, 16);
                    float4 nt = ent_in[t * 16 + l16];
                    if (b + j < deg) add4(A, nt);
                }
            }
            float4 u1 = squash_addi4(A, invd, un);

            A = make_float4(0,0,0,0);
            for (int b = 0; b < mdeg; b += 16) {
                int m = min(16, mdeg - b);
                int idx = b + l16;
                int it = (idx < deg) ? items[s + idx] : 0;
                for (int j = 0; j < m; j++) {
                    int t = __shfl_sync(0xffffffffu, it, j, 16);
                    float4 nt = ent_in[t * 16 + l16];
                    float d = wsum16(dot4(u1, nt));
                    if (b + j < deg) fma4(A, d, nt);
                }
            }
            float4 u2 = squash_addi4(A, invd, un);

            A = make_float4(0,0,0,0);
            for (int b = 0; b < mdeg; b += 16) {
                int m = min(16, mdeg - b);
                int idx = b + l16;
                int it = (idx < deg) ? items[s + idx] : 0;
                for (int j = 0; j < m; j++) {
                    int t = __shfl_sync(0xffffffffu, it, j, 16);
                    float4 nt = ent_in[t * 16 + l16];
                    float d = wsum16(dot4(u2, nt));
                    if (b + j < deg) fma4(A, d, nt);
                }
            }
            u3 = make_float4(A.x * invd + un.x, A.y * invd + un.y,
                             A.z * invd + un.z, A.w * invd + un.w);
        }

        float sq = wsum16(dot4(u3, u3));
        float in2 = __fdividef(1.0f, fmaxf(sqrtf(sq), 1e-12f));
        float4 o = make_float4(u3.x * in2, u3.y * in2, u3.z * in2, u3.w * in2);
        if (usr_store) usr_store[w * 16 + l16] = o;
        float4 r;
        if (init) r = make_float4(un.x + o.x, un.y + o.y, un.z + o.z, un.w + o.w);
        else {
            r = res_usr[w * 16 + l16];
            r.x += o.x; r.y += o.y; r.z += o.z; r.w += o.w;
        }
        res_usr[w * 16 + l16] = r;
    }
}

// ---------------- launch (5 launches) ----------------
extern "C" void kernel_launch(void* const* d_in, const int* in_sizes, int n_in,
                              void* d_out, int out_size) {
    const float* entity_emb = (const float*)d_in[0];
    const float* user_emb   = (const float*)d_in[1];
    const float* latent     = (const float*)d_in[2];
    const float* relw       = (const float*)d_in[3];
    const float* aggw       = (const float*)d_in[4];
    const int*   eidx       = (const int*)d_in[5];   // [2,E]: head row, then tail row
    const int*   etype      = (const int*)d_in[6];
    const int*   uidx       = (const int*)d_in[7];
    const int*   iidx       = (const int*)d_in[8];
    float* out = (float*)d_out;

    int *p_off_ent, *p_off_usr, *p_packed, *p_items;
    float *p_entB, *p_usrB;
    cudaGetSymbolAddress((void**)&p_off_ent, g_off_ent);
    cudaGetSymbolAddress((void**)&p_off_usr, g_off_usr);
    cudaGetSymbolAddress((void**)&p_packed,  g_packed);
    cudaGetSymbolAddress((void**)&p_items,   g_items);
    cudaGetSymbolAddress((void**)&p_entB,    g_entB);
    cudaGetSymbolAddress((void**)&p_usrB,    g_usrB);

    hist_both_k<<<2048, 256>>>(eidx, uidx, relw, latent);                    // #0
    scan_chain_k<<<TILES_E + TILES_U, 1024>>>();                             // #1
    scatter_both_k<<<2048, 256>>>(eidx, eidx + E_N, etype, uidx, iidx);      // #2

    float4* res_e = (float4*)out;
    float4* res_u = (float4*)(out + (size_t)N_ENT * DIM);

    // hop 0 (#3): base embeddings in; init residual; ZBLK tail blocks re-zero cnt
    fused_hop_k<<<EBLK + UBLK + ZBLK, 256>>>(
        (const float4*)entity_emb, (const float4*)user_emb, aggw, 0, 1,
        p_off_ent, p_packed, p_off_usr, p_items,
        (float4*)p_entB, (float4*)p_usrB, res_e, res_u);

    // hop 1 (#4): hop-0 outputs in; accumulate residual only
    fused_hop_k<<<EBLK + UBLK, 256>>>(
        (const float4*)p_entB, (const float4*)p_usrB, aggw, 1, 0,
        p_off_ent, p_packed, p_off_usr, p_items,
        nullptr, nullptr, res_e, res_u);
}

// round 16
// speedup vs baseline: 1.6762x; 1.1260x over previous
#include <cuda_runtime.h>
#include <math.h>

#define N_ENT 200000
#define N_USR 100000
#define DIM   64
#define E_N   1500000
#define NI_N  1000000
#define N_RELM1 10
#define WPB  8                             // warps per block
#define HPW  2                             // heads per warp (16 lanes each)
#define EBLK (N_ENT / (WPB * HPW))         // 12500 (exact)
#define UBLK (N_USR / (WPB * HPW))         // 6250  (exact)
#define ZBLK 512                           // cnt-rezero blocks appended to hop0 grid
#define BMAX 48                            // degree buckets for pair-balancing sort
#define TILE 4096                          // scan tile (1024 thr x 4)
#define TILES_E ((N_ENT + TILE - 1) / TILE)   // 49
#define TILES_U ((N_USR + TILE - 1) / TILE)   // 25

// ---------------- device scratch (no allocation allowed) ----------------
// Invariant: g_cnt_* are all-zero at entry to kernel_launch (zero-init at load;
// hop0 tail blocks re-zero them after scatter each call). Chain/bucket state is
// re-zeroed by hist_both_k each call before use (stream-ordered).
__device__ int   g_remap[16];
__device__ int   g_cnt_ent[N_ENT];
__device__ int   g_off_ent[N_ENT + 1];
__device__ int   g_cnt_usr[N_USR];
__device__ int   g_off_usr[N_USR + 1];
__device__ int   g_packed[E_N];      // tail | (virt<<18)
__device__ int   g_items[NI_N];
__device__ unsigned long long g_pref_ent[TILES_E];
__device__ unsigned long long g_pref_usr[TILES_U];
__device__ int   g_bkt_ent[BMAX];
__device__ int   g_bkt_usr[BMAX];
__device__ int   g_done_ent, g_done_usr;
__device__ int   g_boff_ent[BMAX];
__device__ int   g_bcur_ent[BMAX];
__device__ int   g_boff_usr[BMAX];
__device__ int   g_bcur_usr[BMAX];
__device__ int   g_perm_ent[N_ENT]; // head ids sorted by degree (pair-balanced)
__device__ int   g_perm_usr[N_USR];
__device__ float g_entB[N_ENT * DIM];
__device__ float g_usrB[N_USR * DIM];

// ---------------- helpers ----------------
__device__ __forceinline__ float wsum16(float v) {
    #pragma unroll
    for (int o = 8; o > 0; o >>= 1) v += __shfl_xor_sync(0xffffffffu, v, o);
    return v;
}
__device__ __forceinline__ float dot4(float4 a, float4 b) {
    return a.x * b.x + a.y * b.y + a.z * b.z + a.w * b.w;
}
__device__ __forceinline__ void add4(float4& A, float4 n) {
    A.x += n.x; A.y += n.y; A.z += n.z; A.w += n.w;
}
__device__ __forceinline__ void fma4(float4& A, float s, float4 n) {
    A.x += s * n.x; A.y += s * n.y; A.z += s * n.z; A.w += s * n.w;
}
__device__ __forceinline__ float4 squash_addi4(float4 A, float inv, float4 base) {
    float4 u = make_float4(A.x * inv, A.y * inv, A.z * inv, A.w * inv);
    float sq = wsum16(dot4(u, u));
    float s = __fdividef(sq, (sq + 1.0f) * fmaxf(sqrtf(sq), 1e-12f));
    return make_float4(u.x * s + base.x, u.y * s + base.y,
                       u.z * s + base.z, u.w * s + base.w);
}

// ---------------- preprocessing (3 launches) ----------------

// L0: degree histograms + remap + zero chain/bucket state for this call
__global__ void __launch_bounds__(256)
hist_both_k(const int* __restrict__ heads, const int* __restrict__ uidx,
            const float* __restrict__ relw, const float* __restrict__ lat) {
    int gi = blockIdx.x * blockDim.x + threadIdx.x;
    if (gi < N_RELM1) {
        float best = -1e30f; int bi = 0;
        for (int v = 0; v < 3; v++) {
            float sdot = 0.f;
            #pragma unroll 1
            for (int k = 0; k < DIM; k++) sdot += relw[gi * DIM + k] * lat[v * DIM + k];
            if (sdot > best) { best = sdot; bi = v; }
        }
        g_remap[gi] = bi;
    }
    if (gi < TILES_E) g_pref_ent[gi] = 0ULL;
    if (gi < TILES_U) g_pref_usr[gi] = 0ULL;
    if (gi < BMAX) { g_bkt_ent[gi] = 0; g_bkt_usr[gi] = 0; }
    if (gi == 0) { g_done_ent = 0; g_done_usr = 0; }
    int total = E_N + NI_N;
    for (int i = gi; i < total; i += gridDim.x * blockDim.x) {
        if (i < E_N) atomicAdd(&g_cnt_ent[heads[i]], 1);
        else         atomicAdd(&g_cnt_usr[uidx[i - E_N]], 1);
    }
}

// L1: 74-block chained scan: exclusive CSR offsets + re-zero cnt + degree-bucket
// histogram; the last-done block of each array computes bucket offsets/cursors.
__global__ void __launch_bounds__(1024) scan_chain_k() {
    bool isEnt = blockIdx.x < TILES_E;
    int tile    = isEnt ? blockIdx.x : blockIdx.x - TILES_E;
    int n       = isEnt ? N_ENT : N_USR;
    int ntiles  = isEnt ? TILES_E : TILES_U;
    int* cnt    = isEnt ? g_cnt_ent : g_cnt_usr;
    int* off    = isEnt ? g_off_ent : g_off_usr;
    unsigned long long* pref = isEnt ? g_pref_ent : g_pref_usr;
    int* bkt    = isEnt ? g_bkt_ent : g_bkt_usr;

    const int tid = threadIdx.x, lane = tid & 31, wid = tid >> 5;
    __shared__ int wsh[32];
    __shared__ unsigned long long sprev;
    __shared__ int shb[BMAX];
    __shared__ int sb2[BMAX];
    __shared__ int slast;
    if (tid < BMAX) shb[tid] = 0;
    __syncthreads();

    int i0 = tile * TILE + tid * 4;
    int a0 = 0, a1 = 0, a2 = 0, a3 = 0;
    if (i0 < n)     a0 = cnt[i0];
    if (i0 + 1 < n) a1 = cnt[i0 + 1];
    if (i0 + 2 < n) a2 = cnt[i0 + 2];
    if (i0 + 3 < n) a3 = cnt[i0 + 3];
    if (i0 < n)     atomicAdd(&shb[min(a0, BMAX - 1)], 1);
    if (i0 + 1 < n) atomicAdd(&shb[min(a1, BMAX - 1)], 1);
    if (i0 + 2 < n) atomicAdd(&shb[min(a2, BMAX - 1)], 1);
    if (i0 + 3 < n) atomicAdd(&shb[min(a3, BMAX - 1)], 1);

    int tsum = a0 + a1 + a2 + a3;
    int x = tsum;
    #pragma unroll
    for (int o = 1; o < 32; o <<= 1) {
        int t = __shfl_up_sync(0xffffffffu, x, o);
        if (lane >= o) x += t;
    }
    if (lane == 31) wsh[wid] = x;
    __syncthreads();
    if (wid == 0) {
        int y = wsh[lane];
        #pragma unroll
        for (int o = 1; o < 32; o <<= 1) {
            int t = __shfl_up_sync(0xffffffffu, y, o);
            if (lane >= o) y += t;
        }
        wsh[lane] = y;
    }
    __syncthreads();
    int blockTotal = wsh[31];
    int warpoff = (wid > 0) ? wsh[wid - 1] : 0;
    int incl = x + warpoff;

    // chained prefix: wait for predecessor, publish own inclusive prefix
    if (tid == 0) {
        unsigned long long p = 0ULL;
        if (tile > 0) {
            while (((p = atomicAdd(&pref[tile - 1], 0ULL)) >> 63) == 0ULL) {}
            p &= 0x7FFFFFFFFFFFFFFFULL;
        }
        sprev = p;
        atomicExch(&pref[tile], (1ULL << 63) | (p + (unsigned long long)blockTotal));
        if (tile == ntiles - 1) off[n] = (int)(p + (unsigned long long)blockTotal);
    }
    __syncthreads();
    int carry = (int)sprev;
    int ex = carry + incl - tsum;
    if (i0 < n)     { off[i0]     = ex;                 cnt[i0]     = 0; }
    if (i0 + 1 < n) { off[i0 + 1] = ex + a0;            cnt[i0 + 1] = 0; }
    if (i0 + 2 < n) { off[i0 + 2] = ex + a0 + a1;       cnt[i0 + 2] = 0; }
    if (i0 + 3 < n) { off[i0 + 3] = ex + a0 + a1 + a2;  cnt[i0 + 3] = 0; }

    // bucket histogram to global; last-done block computes boff/bcur
    if (tid < BMAX && shb[tid]) atomicAdd(&bkt[tid], shb[tid]);
    if (tid == 0) {
        __threadfence();
        int done = atomicAdd(isEnt ? &g_done_ent : &g_done_usr, 1);
        slast = (done == ntiles - 1);
    }
    __syncthreads();
    if (slast) {
        if (tid < BMAX) sb2[tid] = atomicAdd(&bkt[tid], 0);
        __syncthreads();
        if (tid == 0) {
            int* boff = isEnt ? g_boff_ent : g_boff_usr;
            int* bcur = isEnt ? g_bcur_ent : g_bcur_usr;
            int acc = 0;
            for (int b = 0; b < BMAX; b++) { boff[b] = acc; acc += sb2[b]; bcur[b] = 0; }
        }
    }
}

// L2: scatter edges + user items into CSR; warp-aggregated counting-sort of node
// ids by degree into perm.
__global__ void __launch_bounds__(256)
scatter_both_k(const int* __restrict__ heads, const int* __restrict__ tails,
               const int* __restrict__ et,
               const int* __restrict__ uidx, const int* __restrict__ iidx) {
    int total = E_N + NI_N + N_ENT + N_USR;
    for (int i = blockIdx.x * blockDim.x + threadIdx.x; i < total; i += gridDim.x * blockDim.x) {
        if (i < E_N) {
            int h = heads[i];
            int pos = g_off_ent[h] + atomicAdd(&g_cnt_ent[h], 1);
            int v = g_remap[et[i] - 1];
            g_packed[pos] = tails[i] | (v << 18);
        } else if (i < E_N + NI_N) {
            int k = i - E_N;
            int u = uidx[k];
            int pos = g_off_usr[u] + atomicAdd(&g_cnt_usr[u], 1);
            g_items[pos] = iidx[k];
        } else {
            int h = i - (E_N + NI_N);
            bool ent = (h < N_ENT);
            if (!ent) h -= N_ENT;
            int deg = ent ? (g_off_ent[h + 1] - g_off_ent[h])
                          : (g_off_usr[h + 1] - g_off_usr[h]);
            int b = min(deg, BMAX - 1);
            int key = b | (ent ? 64 : 0);
            unsigned am = __activemask();
            unsigned mk = __match_any_sync(am, key);
            int lanei = threadIdx.x & 31;
            int leader = __ffs(mk) - 1;
            int rank = __popc(mk & ((1u << lanei) - 1));
            int base = 0;
            if (lanei == leader)
                base = atomicAdd(ent ? &g_bcur_ent[b] : &g_bcur_usr[b], __popc(mk));
            base = __shfl_sync(mk, base, leader);
            int pos = (ent ? g_boff_ent : g_boff_usr)[b] + base + rank;
            if (ent) g_perm_ent[pos] = h; else g_perm_usr[pos] = h;
        }
    }
}

// ---------------- fused hop kernel: 2 degree-matched heads per warp ----------------
// __launch_bounds__(256, 5): single-knob experiment — cap regs at ~51 to fit 5
// blocks/SM (40 warps, 62.5% theor. occ). R15 sat at 64 regs / 4 blocks / 45.5% occ,
// issue 60.8%. Revert to (256, 4) if this spills into the inner loop.
__global__ void __launch_bounds__(256, 5)
fused_hop_k(const float4* __restrict__ ent_in, const float4* __restrict__ usr_in,
            const float* __restrict__ aggw, int hop, int init,
            const int* __restrict__ off_e, const int* __restrict__ packed,
            const int* __restrict__ off_u, const int* __restrict__ items,
            float4* __restrict__ ent_store, float4* __restrict__ usr_store,
            float4* __restrict__ res_ent, float4* __restrict__ res_usr)
{
    __shared__ float s_d[WPB][32];     // pass-1 dots: [warp][half*16 + j]

    const int wid  = threadIdx.x >> 5;
    const int lane = threadIdx.x & 31;
    const int l16  = lane & 15;
    const int half = lane >> 4;
    float* __restrict__ sd = &s_d[wid][half * 16];

    if (blockIdx.x >= EBLK + UBLK) {
        // cnt re-zero duty (hop0 only): restore the all-zero invariant
        int i = (blockIdx.x - (EBLK + UBLK)) * 256 + threadIdx.x;
        for (; i < N_ENT + N_USR; i += ZBLK * 256) {
            if (i < N_ENT) g_cnt_ent[i] = 0;
            else           g_cnt_usr[i - N_ENT] = 0;
        }
        return;
    }

    if (blockIdx.x < EBLK) {
        // ======================= ENTITY (2 degree-matched heads / warp) ========
        int slot = (blockIdx.x * WPB + wid) * HPW + half;
        int w = g_perm_ent[slot];                        // degree-sorted head id

        float4 en = ent_in[w * 16 + l16];
        int s = off_e[w], e = off_e[w + 1];
        int deg = e - s;
        int mdeg = max(deg, __shfl_xor_sync(0xffffffffu, deg, 16));  // ~= deg now

        float a0 = aggw[hop * 3 + 0], a1 = aggw[hop * 3 + 1], a2 = aggw[hop * 3 + 2];
        float mx = fmaxf(a0, fmaxf(a1, a2));
        float e0 = __expf(a0 - mx), e1 = __expf(a1 - mx), e2 = __expf(a2 - mx);
        float inv = __fdividef(1.0f, e0 + e1 + e2);
        float w0 = e0 * inv, w1 = e1 * inv, w2 = e2 * inv;

        float4 u30, u31, u32;

        if (mdeg <= 16) {
            // ---------- fast path: own half's edges resident in one register ----------
            int pk = (l16 < deg) ? packed[s + l16] : 0;

            // pass 0
            float4 A0 = {0,0,0,0}, A1 = {0,0,0,0}, A2 = {0,0,0,0};
            int c0 = 0, c1 = 0, c2 = 0;
            for (int j = 0; j < mdeg; j++) {
                int p = __shfl_sync(0xffffffffu, pk, j, 16);
                int t = p & 0x3FFFF, v = p >> 18;
                float4 nt = ent_in[t * 16 + l16];
                if (j < deg) {
                    if (v == 0)      { add4(A0, nt); c0++; }
                    else if (v == 1) { add4(A1, nt); c1++; }
                    else             { add4(A2, nt); c2++; }
                }
            }
            float i0 = __fdividef(1.f, fmaxf((float)c0, 1.f));
            float i1 = __fdividef(1.f, fmaxf((float)c1, 1.f));
            float i2 = __fdividef(1.f, fmaxf((float)c2, 1.f));
            float4 u10 = squash_addi4(A0, i0, en);
            float4 u11 = squash_addi4(A1, i1, en);
            float4 u12 = squash_addi4(A2, i2, en);

            // pass 1: dots cached in sd
            A0 = make_float4(0,0,0,0); A1 = make_float4(0,0,0,0); A2 = make_float4(0,0,0,0);
            for (int j = 0; j < mdeg; j++) {
                int p = __shfl_sync(0xffffffffu, pk, j, 16);
                int t = p & 0x3FFFF, v = p >> 18;
                float4 nt = ent_in[t * 16 + l16];
                float4 uv = (v == 0) ? u10 : ((v == 1) ? u11 : u12);
                float d = wsum16(dot4(uv, nt));
                if (j < deg) {
                    if (l16 == 0) sd[j] = d;
                    if (v == 0)      fma4(A0, d, nt);
                    else if (v == 1) fma4(A1, d, nt);
                    else             fma4(A2, d, nt);
                }
            }
            float4 u20 = squash_addi4(A0, i0, en);
            float4 u21 = squash_addi4(A1, i1, en);
            float4 u22 = squash_addi4(A2, i2, en);

            __syncwarp();

            // pass 2: scale = d1^2 * d2 (d1 from sd; u1x dead here)
            A0 = make_float4(0,0,0,0); A1 = make_float4(0,0,0,0); A2 = make_float4(0,0,0,0);
            for (int j = 0; j < mdeg; j++) {
                int p = __shfl_sync(0xffffffffu, pk, j, 16);
                int t = p & 0x3FFFF, v = p >> 18;
                float4 nt = ent_in[t * 16 + l16];
                float4 uB = (v == 0) ? u20 : ((v == 1) ? u21 : u22);
                float pb = wsum16(dot4(uB, nt));
                if (j < deg) {
                    float pa = sd[j];
                    float sc = pa * pa * pb;
                    if (v == 0)      fma4(A0, sc, nt);
                    else if (v == 1) fma4(A1, sc, nt);
                    else             fma4(A2, sc, nt);
                }
            }
            u30 = make_float4(A0.x * i0 + en.x, A0.y * i0 + en.y, A0.z * i0 + en.z, A0.w * i0 + en.w);
            u31 = make_float4(A1.x * i1 + en.x, A1.y * i1 + en.y, A1.z * i1 + en.z, A1.w * i1 + en.w);
            u32 = make_float4(A2.x * i2 + en.x, A2.y * i2 + en.y, A2.z * i2 + en.z, A2.w * i2 + en.w);
        } else {
            // ---------- generic path (rare mdeg > 16) ----------
            float4 A0 = {0,0,0,0}, A1 = {0,0,0,0}, A2 = {0,0,0,0};
            int c0 = 0, c1 = 0, c2 = 0;
            for (int b = 0; b < mdeg; b += 16) {
                int m = min(16, mdeg - b);
                int idx = b + l16;
                int pk = (idx < deg) ? packed[s + idx] : 0;
                for (int j = 0; j < m; j++) {
                    int p = __shfl_sync(0xffffffffu, pk, j, 16);
                    int t = p & 0x3FFFF, v = p >> 18;
                    float4 nt = ent_in[t * 16 + l16];
                    if (b + j < deg) {
                        if (v == 0)      { add4(A0, nt); c0++; }
                        else if (v == 1) { add4(A1, nt); c1++; }
                        else             { add4(A2, nt); c2++; }
                    }
                }
            }
            float i0 = __fdividef(1.f, fmaxf((float)c0, 1.f));
            float i1 = __fdividef(1.f, fmaxf((float)c1, 1.f));
            float i2 = __fdividef(1.f, fmaxf((float)c2, 1.f));
            float4 u10 = squash_addi4(A0, i0, en);
            float4 u11 = squash_addi4(A1, i1, en);
            float4 u12 = squash_addi4(A2, i2, en);

            A0 = make_float4(0,0,0,0); A1 = make_float4(0,0,0,0); A2 = make_float4(0,0,0,0);
            for (int b = 0; b < mdeg; b += 16) {
                int m = min(16, mdeg - b);
                int idx = b + l16;
                int pk = (idx < deg) ? packed[s + idx] : 0;
                for (int j = 0; j < m; j++) {
                    int p = __shfl_sync(0xffffffffu, pk, j, 16);
                    int t = p & 0x3FFFF, v = p >> 18;
                    float4 nt = ent_in[t * 16 + l16];
                    float4 uv = (v == 0) ? u10 : ((v == 1) ? u11 : u12);
                    float d = wsum16(dot4(uv, nt));
                    if (b + j < deg) {
                        if (v == 0)      fma4(A0, d, nt);
                        else if (v == 1) fma4(A1, d, nt);
                        else             fma4(A2, d, nt);
                    }
                }
            }
            float4 u20 = squash_addi4(A0, i0, en);
            float4 u21 = squash_addi4(A1, i1, en);
            float4 u22 = squash_addi4(A2, i2, en);

            A0 = make_float4(0,0,0,0); A1 = make_float4(0,0,0,0); A2 = make_float4(0,0,0,0);
            for (int b = 0; b < mdeg; b += 16) {
                int m = min(16, mdeg - b);
                int idx = b + l16;
                int pk = (idx < deg) ? packed[s + idx] : 0;
                for (int j = 0; j < m; j++) {
                    int p = __shfl_sync(0xffffffffu, pk, j, 16);
                    int t = p & 0x3FFFF, v = p >> 18;
                    float4 nt = ent_in[t * 16 + l16];
                    float4 uA = (v == 0) ? u10 : ((v == 1) ? u11 : u12);
                    float4 uB = (v == 0) ? u20 : ((v == 1) ? u21 : u22);
                    float pa = dot4(uA, nt);
                    float pb = dot4(uB, nt);
                    #pragma unroll
                    for (int o = 8; o > 0; o >>= 1) {
                        pa += __shfl_xor_sync(0xffffffffu, pa, o);
                        pb += __shfl_xor_sync(0xffffffffu, pb, o);
                    }
                    if (b + j < deg) {
                        float sc = pa * pa * pb;
                        if (v == 0)      fma4(A0, sc, nt);
                        else if (v == 1) fma4(A1, sc, nt);
                        else             fma4(A2, sc, nt);
                    }
                }
            }
            u30 = make_float4(A0.x * i0 + en.x, A0.y * i0 + en.y, A0.z * i0 + en.z, A0.w * i0 + en.w);
            u31 = make_float4(A1.x * i1 + en.x, A1.y * i1 + en.y, A1.z * i1 + en.z, A1.w * i1 + en.w);
            u32 = make_float4(A2.x * i2 + en.x, A2.y * i2 + en.y, A2.z * i2 + en.z, A2.w * i2 + en.w);
        }

        // weighted agg + l2norm + residual
        float4 ag = make_float4(w0 * u30.x + w1 * u31.x + w2 * u32.x,
                                w0 * u30.y + w1 * u31.y + w2 * u32.y,
                                w0 * u30.z + w1 * u31.z + w2 * u32.z,
                                w0 * u30.w + w1 * u31.w + w2 * u32.w);
        float sq = wsum16(dot4(ag, ag));
        float in2 = __fdividef(1.0f, fmaxf(sqrtf(sq), 1e-12f));
        float4 o = make_float4(ag.x * in2, ag.y * in2, ag.z * in2, ag.w * in2);
        if (ent_store) ent_store[w * 16 + l16] = o;
        float4 r;
        if (init) r = make_float4(en.x + o.x, en.y + o.y, en.z + o.z, en.w + o.w);
        else {
            r = res_ent[w * 16 + l16];
            r.x += o.x; r.y += o.y; r.z += o.z; r.w += o.w;
        }
        res_ent[w * 16 + l16] = r;

    } else {
        // ======================= USER (2 degree-matched users / warp) ==========
        int slot = ((blockIdx.x - EBLK) * WPB + wid) * HPW + half;
        int w = g_perm_usr[slot];                        // degree-sorted user id

        float4 un = usr_in[w * 16 + l16];
        int s = off_u[w], e = off_u[w + 1];
        int deg = e - s;
        int mdeg = max(deg, __shfl_xor_sync(0xffffffffu, deg, 16));
        float invd = __fdividef(1.f, fmaxf((float)deg, 1.f));
        float4 u3;

        if (mdeg <= 16) {
            // ---------- fast path ----------
            int it = (l16 < deg) ? items[s + l16] : 0;

            float4 A = {0,0,0,0};
            for (int j = 0; j < mdeg; j++) {
                int t = __shfl_sync(0xffffffffu, it, j, 16);
                float4 nt = ent_in[t * 16 + l16];
                if (j < deg) add4(A, nt);
            }
            float4 u1 = squash_addi4(A, invd, un);

            A = make_float4(0,0,0,0);
            for (int j = 0; j < mdeg; j++) {
                int t = __shfl_sync(0xffffffffu, it, j, 16);
                float4 nt = ent_in[t * 16 + l16];
                float d = wsum16(dot4(u1, nt));
                if (j < deg) fma4(A, d, nt);
            }
            float4 u2 = squash_addi4(A, invd, un);

            A = make_float4(0,0,0,0);
            for (int j = 0; j < mdeg; j++) {
                int t = __shfl_sync(0xffffffffu, it, j, 16);
                float4 nt = ent_in[t * 16 + l16];
                float d = wsum16(dot4(u2, nt));
                if (j < deg) fma4(A, d, nt);
            }
            u3 = make_float4(A.x * invd + un.x, A.y * invd + un.y,
                             A.z * invd + un.z, A.w * invd + un.w);
        } else {
            // ---------- generic path ----------
            float4 A = {0,0,0,0};
            for (int b = 0; b < mdeg; b += 16) {
                int m = min(16, mdeg - b);
                int idx = b + l16;
                int it = (idx < deg) ? items[s + idx] : 0;
                for (int j = 0; j < m; j++) {
                    int t = __shfl_sync(0xffffffffu, it, j, 16);
                    float4 nt = ent_in[t * 16 + l16];
                    if (b + j < deg) add4(A, nt);
                }
            }
            float4 u1 = squash_addi4(A, invd, un);

            A = make_float4(0,0,0,0);
            for (int b = 0; b < mdeg; b += 16) {
                int m = min(16, mdeg - b);
                int idx = b + l16;
                int it = (idx < deg) ? items[s + idx] : 0;
                for (int j = 0; j < m; j++) {
                    int t = __shfl_sync(0xffffffffu, it, j, 16);
                    float4 nt = ent_in[t * 16 + l16];
                    float d = wsum16(dot4(u1, nt));
                    if (b + j < deg) fma4(A, d, nt);
                }
            }
            float4 u2 = squash_addi4(A, invd, un);

            A = make_float4(0,0,0,0);
            for (int b = 0; b < mdeg; b += 16) {
                int m = min(16, mdeg - b);
                int idx = b + l16;
                int it = (idx < deg) ? items[s + idx] : 0;
                for (int j = 0; j < m; j++) {
                    int t = __shfl_sync(0xffffffffu, it, j, 16);
                    float4 nt = ent_in[t * 16 + l16];
                    float d = wsum16(dot4(u2, nt));
                    if (b + j < deg) fma4(A, d, nt);
                }
            }
            u3 = make_float4(A.x * invd + un.x, A.y * invd + un.y,
                             A.z * invd + un.z, A.w * invd + un.w);
        }

        float sq = wsum16(dot4(u3, u3));
        float in2 = __fdividef(1.0f, fmaxf(sqrtf(sq), 1e-12f));
        float4 o = make_float4(u3.x * in2, u3.y * in2, u3.z * in2, u3.w * in2);
        if (usr_store) usr_store[w * 16 + l16] = o;
        float4 r;
        if (init) r = make_float4(un.x + o.x, un.y + o.y, un.z + o.z, un.w + o.w);
        else {
            r = res_usr[w * 16 + l16];
            r.x += o.x; r.y += o.y; r.z += o.z; r.w += o.w;
        }
        res_usr[w * 16 + l16] = r;
    }
}

// ---------------- launch (5 launches) ----------------
extern "C" void kernel_launch(void* const* d_in, const int* in_sizes, int n_in,
                              void* d_out, int out_size) {
    const float* entity_emb = (const float*)d_in[0];
    const float* user_emb   = (const float*)d_in[1];
    const float* latent     = (const float*)d_in[2];
    const float* relw       = (const float*)d_in[3];
    const float* aggw       = (const float*)d_in[4];
    const int*   eidx       = (const int*)d_in[5];   // [2,E]: head row, then tail row
    const int*   etype      = (const int*)d_in[6];
    const int*   uidx       = (const int*)d_in[7];
    const int*   iidx       = (const int*)d_in[8];
    float* out = (float*)d_out;

    int *p_off_ent, *p_off_usr, *p_packed, *p_items;
    float *p_entB, *p_usrB;
    cudaGetSymbolAddress((void**)&p_off_ent, g_off_ent);
    cudaGetSymbolAddress((void**)&p_off_usr, g_off_usr);
    cudaGetSymbolAddress((void**)&p_packed,  g_packed);
    cudaGetSymbolAddress((void**)&p_items,   g_items);
    cudaGetSymbolAddress((void**)&p_entB,    g_entB);
    cudaGetSymbolAddress((void**)&p_usrB,    g_usrB);

    hist_both_k<<<2048, 256>>>(eidx, uidx, relw, latent);                    // #0
    scan_chain_k<<<TILES_E + TILES_U, 1024>>>();                             // #1
    scatter_both_k<<<2048, 256>>>(eidx, eidx + E_N, etype, uidx, iidx);      // #2

    float4* res_e = (float4*)out;
    float4* res_u = (float4*)(out + (size_t)N_ENT * DIM);

    // hop 0 (#3): base embeddings in; init residual; ZBLK tail blocks re-zero cnt
    fused_hop_k<<<EBLK + UBLK + ZBLK, 256>>>(
        (const float4*)entity_emb, (const float4*)user_emb, aggw, 0, 1,
        p_off_ent, p_packed, p_off_usr, p_items,
        (float4*)p_entB, (float4*)p_usrB, res_e, res_u);

    // hop 1 (#4): hop-0 outputs in; accumulate residual only
    fused_hop_k<<<EBLK + UBLK, 256>>>(
        (const float4*)p_entB, (const float4*)p_usrB, aggw, 1, 0,
        p_off_ent, p_packed, p_off_usr, p_items,
        nullptr, nullptr, res_e, res_u);
}

// round 17
// speedup vs baseline: 1.6768x; 1.0003x over previous
#include <cuda_runtime.h>
#include <math.h>

#define N_ENT 200000
#define N_USR 100000
#define DIM   64
#define E_N   1500000
#define NI_N  1000000
#define N_RELM1 10
#define WPB  8                             // warps per block
#define HPW  2                             // heads per warp (16 lanes each)
#define EBLK (N_ENT / (WPB * HPW))         // 12500 (exact)
#define UBLK (N_USR / (WPB * HPW))         // 6250  (exact)
#define ZBLK 512                           // cnt-rezero blocks appended to hop0 grid
#define BMAX 48                            // degree buckets for pair-balancing sort
#define TILE 4096                          // scan tile (1024 thr x 4)
#define TILES_E ((N_ENT + TILE - 1) / TILE)   // 49
#define TILES_U ((N_USR + TILE - 1) / TILE)   // 25

// ---------------- device scratch (no allocation allowed) ----------------
// Invariant: g_cnt_* are all-zero at entry to kernel_launch (zero-init at load;
// hop0 tail blocks re-zero them after scatter each call). Chain/bucket state is
// re-zeroed by hist_both_k each call before use (stream-ordered).
__device__ int   g_remap[16];
__device__ int   g_cnt_ent[N_ENT];
__device__ int   g_off_ent[N_ENT + 1];
__device__ int   g_cnt_usr[N_USR];
__device__ int   g_off_usr[N_USR + 1];
__device__ int   g_packed[E_N];      // tail | (virt<<18)
__device__ int   g_items[NI_N];
__device__ unsigned long long g_pref_ent[TILES_E];
__device__ unsigned long long g_pref_usr[TILES_U];
__device__ int   g_bkt_ent[BMAX];
__device__ int   g_bkt_usr[BMAX];
__device__ int   g_done_ent, g_done_usr;
__device__ int   g_boff_ent[BMAX];
__device__ int   g_bcur_ent[BMAX];
__device__ int   g_boff_usr[BMAX];
__device__ int   g_bcur_usr[BMAX];
__device__ int   g_perm_ent[N_ENT]; // head ids sorted by degree (pair-balanced)
__device__ int   g_perm_usr[N_USR];
__device__ float g_entB[N_ENT * DIM];
__device__ float g_usrB[N_USR * DIM];

// ---------------- helpers ----------------
__device__ __forceinline__ float wsum16(float v) {
    #pragma unroll
    for (int o = 8; o > 0; o >>= 1) v += __shfl_xor_sync(0xffffffffu, v, o);
    return v;
}
__device__ __forceinline__ float dot4(float4 a, float4 b) {
    return a.x * b.x + a.y * b.y + a.z * b.z + a.w * b.w;
}
__device__ __forceinline__ void add4(float4& A, float4 n) {
    A.x += n.x; A.y += n.y; A.z += n.z; A.w += n.w;
}
__device__ __forceinline__ void fma4(float4& A, float s, float4 n) {
    A.x += s * n.x; A.y += s * n.y; A.z += s * n.z; A.w += s * n.w;
}
__device__ __forceinline__ float4 squash_addi4(float4 A, float inv, float4 base) {
    float4 u = make_float4(A.x * inv, A.y * inv, A.z * inv, A.w * inv);
    float sq = wsum16(dot4(u, u));
    float s = __fdividef(sq, (sq + 1.0f) * fmaxf(sqrtf(sq), 1e-12f));
    return make_float4(u.x * s + base.x, u.y * s + base.y,
                       u.z * s + base.z, u.w * s + base.w);
}

// ---------------- preprocessing (3 launches) ----------------

// L0: degree histograms + remap + zero chain/bucket state for this call
__global__ void __launch_bounds__(256)
hist_both_k(const int* __restrict__ heads, const int* __restrict__ uidx,
            const float* __restrict__ relw, const float* __restrict__ lat) {
    int gi = blockIdx.x * blockDim.x + threadIdx.x;
    if (gi < N_RELM1) {
        float best = -1e30f; int bi = 0;
        for (int v = 0; v < 3; v++) {
            float sdot = 0.f;
            #pragma unroll 1
            for (int k = 0; k < DIM; k++) sdot += relw[gi * DIM + k] * lat[v * DIM + k];
            if (sdot > best) { best = sdot; bi = v; }
        }
        g_remap[gi] = bi;
    }
    if (gi < TILES_E) g_pref_ent[gi] = 0ULL;
    if (gi < TILES_U) g_pref_usr[gi] = 0ULL;
    if (gi < BMAX) { g_bkt_ent[gi] = 0; g_bkt_usr[gi] = 0; }
    if (gi == 0) { g_done_ent = 0; g_done_usr = 0; }
    int total = E_N + NI_N;
    for (int i = gi; i < total; i += gridDim.x * blockDim.x) {
        if (i < E_N) atomicAdd(&g_cnt_ent[heads[i]], 1);
        else         atomicAdd(&g_cnt_usr[uidx[i - E_N]], 1);
    }
}

// L1: 74-block chained scan: exclusive CSR offsets + re-zero cnt + degree-bucket
// histogram; the last-done block of each array computes bucket offsets/cursors.
__global__ void __launch_bounds__(1024) scan_chain_k() {
    bool isEnt = blockIdx.x < TILES_E;
    int tile    = isEnt ? blockIdx.x : blockIdx.x - TILES_E;
    int n       = isEnt ? N_ENT : N_USR;
    int ntiles  = isEnt ? TILES_E : TILES_U;
    int* cnt    = isEnt ? g_cnt_ent : g_cnt_usr;
    int* off    = isEnt ? g_off_ent : g_off_usr;
    unsigned long long* pref = isEnt ? g_pref_ent : g_pref_usr;
    int* bkt    = isEnt ? g_bkt_ent : g_bkt_usr;

    const int tid = threadIdx.x, lane = tid & 31, wid = tid >> 5;
    __shared__ int wsh[32];
    __shared__ unsigned long long sprev;
    __shared__ int shb[BMAX];
    __shared__ int sb2[BMAX];
    __shared__ int slast;
    if (tid < BMAX) shb[tid] = 0;
    __syncthreads();

    int i0 = tile * TILE + tid * 4;
    int a0 = 0, a1 = 0, a2 = 0, a3 = 0;
    if (i0 < n)     a0 = cnt[i0];
    if (i0 + 1 < n) a1 = cnt[i0 + 1];
    if (i0 + 2 < n) a2 = cnt[i0 + 2];
    if (i0 + 3 < n) a3 = cnt[i0 + 3];
    if (i0 < n)     atomicAdd(&shb[min(a0, BMAX - 1)], 1);
    if (i0 + 1 < n) atomicAdd(&shb[min(a1, BMAX - 1)], 1);
    if (i0 + 2 < n) atomicAdd(&shb[min(a2, BMAX - 1)], 1);
    if (i0 + 3 < n) atomicAdd(&shb[min(a3, BMAX - 1)], 1);

    int tsum = a0 + a1 + a2 + a3;
    int x = tsum;
    #pragma unroll
    for (int o = 1; o < 32; o <<= 1) {
        int t = __shfl_up_sync(0xffffffffu, x, o);
        if (lane >= o) x += t;
    }
    if (lane == 31) wsh[wid] = x;
    __syncthreads();
    if (wid == 0) {
        int y = wsh[lane];
        #pragma unroll
        for (int o = 1; o < 32; o <<= 1) {
            int t = __shfl_up_sync(0xffffffffu, y, o);
            if (lane >= o) y += t;
        }
        wsh[lane] = y;
    }
    __syncthreads();
    int blockTotal = wsh[31];
    int warpoff = (wid > 0) ? wsh[wid - 1] : 0;
    int incl = x + warpoff;

    // chained prefix: wait for predecessor, publish own inclusive prefix
    if (tid == 0) {
        unsigned long long p = 0ULL;
        if (tile > 0) {
            while (((p = atomicAdd(&pref[tile - 1], 0ULL)) >> 63) == 0ULL) {}
            p &= 0x7FFFFFFFFFFFFFFFULL;
        }
        sprev = p;
        atomicExch(&pref[tile], (1ULL << 63) | (p + (unsigned long long)blockTotal));
        if (tile == ntiles - 1) off[n] = (int)(p + (unsigned long long)blockTotal);
    }
    __syncthreads();
    int carry = (int)sprev;
    int ex = carry + incl - tsum;
    if (i0 < n)     { off[i0]     = ex;                 cnt[i0]     = 0; }
    if (i0 + 1 < n) { off[i0 + 1] = ex + a0;            cnt[i0 + 1] = 0; }
    if (i0 + 2 < n) { off[i0 + 2] = ex + a0 + a1;       cnt[i0 + 2] = 0; }
    if (i0 + 3 < n) { off[i0 + 3] = ex + a0 + a1 + a2;  cnt[i0 + 3] = 0; }

    // bucket histogram to global; last-done block computes boff/bcur
    if (tid < BMAX && shb[tid]) atomicAdd(&bkt[tid], shb[tid]);
    if (tid == 0) {
        __threadfence();
        int done = atomicAdd(isEnt ? &g_done_ent : &g_done_usr, 1);
        slast = (done == ntiles - 1);
    }
    __syncthreads();
    if (slast) {
        if (tid < BMAX) sb2[tid] = atomicAdd(&bkt[tid], 0);
        __syncthreads();
        if (tid == 0) {
            int* boff = isEnt ? g_boff_ent : g_boff_usr;
            int* bcur = isEnt ? g_bcur_ent : g_bcur_usr;
            int acc = 0;
            for (int b = 0; b < BMAX; b++) { boff[b] = acc; acc += sb2[b]; bcur[b] = 0; }
        }
    }
}

// L2: scatter edges + user items into CSR; warp-aggregated counting-sort of node
// ids by degree into perm.
__global__ void __launch_bounds__(256)
scatter_both_k(const int* __restrict__ heads, const int* __restrict__ tails,
               const int* __restrict__ et,
               const int* __restrict__ uidx, const int* __restrict__ iidx) {
    int total = E_N + NI_N + N_ENT + N_USR;
    for (int i = blockIdx.x * blockDim.x + threadIdx.x; i < total; i += gridDim.x * blockDim.x) {
        if (i < E_N) {
            int h = heads[i];
            int pos = g_off_ent[h] + atomicAdd(&g_cnt_ent[h], 1);
            int v = g_remap[et[i] - 1];
            g_packed[pos] = tails[i] | (v << 18);
        } else if (i < E_N + NI_N) {
            int k = i - E_N;
            int u = uidx[k];
            int pos = g_off_usr[u] + atomicAdd(&g_cnt_usr[u], 1);
            g_items[pos] = iidx[k];
        } else {
            int h = i - (E_N + NI_N);
            bool ent = (h < N_ENT);
            if (!ent) h -= N_ENT;
            int deg = ent ? (g_off_ent[h + 1] - g_off_ent[h])
                          : (g_off_usr[h + 1] - g_off_usr[h]);
            int b = min(deg, BMAX - 1);
            int key = b | (ent ? 64 : 0);
            unsigned am = __activemask();
            unsigned mk = __match_any_sync(am, key);
            int lanei = threadIdx.x & 31;
            int leader = __ffs(mk) - 1;
            int rank = __popc(mk & ((1u << lanei) - 1));
            int base = 0;
            if (lanei == leader)
                base = atomicAdd(ent ? &g_bcur_ent[b] : &g_bcur_usr[b], __popc(mk));
            base = __shfl_sync(mk, base, leader);
            int pos = (ent ? g_boff_ent : g_boff_usr)[b] + base + rank;
            if (ent) g_perm_ent[pos] = h; else g_perm_usr[pos] = h;
        }
    }
}

// ---------------- fused hop kernel: 2 degree-matched heads per warp ----------------
// __launch_bounds__(256, 6): next occupancy step — cap regs at 42 to fit 6 blocks/SM
// (48 warps, 75% theor. occ). R16: (256,5) gave 48 regs / 57.2% occ / issue 67.5% and
// a clean win. Revert to (256, 5) if spills reach the inner loop.
__global__ void __launch_bounds__(256, 6)
fused_hop_k(const float4* __restrict__ ent_in, const float4* __restrict__ usr_in,
            const float* __restrict__ aggw, int hop, int init,
            const int* __restrict__ off_e, const int* __restrict__ packed,
            const int* __restrict__ off_u, const int* __restrict__ items,
            float4* __restrict__ ent_store, float4* __restrict__ usr_store,
            float4* __restrict__ res_ent, float4* __restrict__ res_usr)
{
    __shared__ float s_d[WPB][32];     // pass-1 dots: [warp][half*16 + j]

    const int wid  = threadIdx.x >> 5;
    const int lane = threadIdx.x & 31;
    const int l16  = lane & 15;
    const int half = lane >> 4;
    float* __restrict__ sd = &s_d[wid][half * 16];

    if (blockIdx.x >= EBLK + UBLK) {
        // cnt re-zero duty (hop0 only): restore the all-zero invariant
        int i = (blockIdx.x - (EBLK + UBLK)) * 256 + threadIdx.x;
        for (; i < N_ENT + N_USR; i += ZBLK * 256) {
            if (i < N_ENT) g_cnt_ent[i] = 0;
            else           g_cnt_usr[i - N_ENT] = 0;
        }
        return;
    }

    if (blockIdx.x < EBLK) {
        // ======================= ENTITY (2 degree-matched heads / warp) ========
        int slot = (blockIdx.x * WPB + wid) * HPW + half;
        int w = g_perm_ent[slot];                        // degree-sorted head id

        float4 en = ent_in[w * 16 + l16];
        int s = off_e[w], e = off_e[w + 1];
        int deg = e - s;
        int mdeg = max(deg, __shfl_xor_sync(0xffffffffu, deg, 16));  // ~= deg now

        float a0 = aggw[hop * 3 + 0], a1 = aggw[hop * 3 + 1], a2 = aggw[hop * 3 + 2];
        float mx = fmaxf(a0, fmaxf(a1, a2));
        float e0 = __expf(a0 - mx), e1 = __expf(a1 - mx), e2 = __expf(a2 - mx);
        float inv = __fdividef(1.0f, e0 + e1 + e2);
        float w0 = e0 * inv, w1 = e1 * inv, w2 = e2 * inv;

        float4 u30, u31, u32;

        if (mdeg <= 16) {
            // ---------- fast path: own half's edges resident in one register ----------
            int pk = (l16 < deg) ? packed[s + l16] : 0;

            // pass 0
            float4 A0 = {0,0,0,0}, A1 = {0,0,0,0}, A2 = {0,0,0,0};
            int c0 = 0, c1 = 0, c2 = 0;
            for (int j = 0; j < mdeg; j++) {
                int p = __shfl_sync(0xffffffffu, pk, j, 16);
                int t = p & 0x3FFFF, v = p >> 18;
                float4 nt = ent_in[t * 16 + l16];
                if (j < deg) {
                    if (v == 0)      { add4(A0, nt); c0++; }
                    else if (v == 1) { add4(A1, nt); c1++; }
                    else             { add4(A2, nt); c2++; }
                }
            }
            float i0 = __fdividef(1.f, fmaxf((float)c0, 1.f));
            float i1 = __fdividef(1.f, fmaxf((float)c1, 1.f));
            float i2 = __fdividef(1.f, fmaxf((float)c2, 1.f));
            float4 u10 = squash_addi4(A0, i0, en);
            float4 u11 = squash_addi4(A1, i1, en);
            float4 u12 = squash_addi4(A2, i2, en);

            // pass 1: dots cached in sd
            A0 = make_float4(0,0,0,0); A1 = make_float4(0,0,0,0); A2 = make_float4(0,0,0,0);
            for (int j = 0; j < mdeg; j++) {
                int p = __shfl_sync(0xffffffffu, pk, j, 16);
                int t = p & 0x3FFFF, v = p >> 18;
                float4 nt = ent_in[t * 16 + l16];
                float4 uv = (v == 0) ? u10 : ((v == 1) ? u11 : u12);
                float d = wsum16(dot4(uv, nt));
                if (j < deg) {
                    if (l16 == 0) sd[j] = d;
                    if (v == 0)      fma4(A0, d, nt);
                    else if (v == 1) fma4(A1, d, nt);
                    else             fma4(A2, d, nt);
                }
            }
            float4 u20 = squash_addi4(A0, i0, en);
            float4 u21 = squash_addi4(A1, i1, en);
            float4 u22 = squash_addi4(A2, i2, en);

            __syncwarp();

            // pass 2: scale = d1^2 * d2 (d1 from sd; u1x dead here)
            A0 = make_float4(0,0,0,0); A1 = make_float4(0,0,0,0); A2 = make_float4(0,0,0,0);
            for (int j = 0; j < mdeg; j++) {
                int p = __shfl_sync(0xffffffffu, pk, j, 16);
                int t = p & 0x3FFFF, v = p >> 18;
                float4 nt = ent_in[t * 16 + l16];
                float4 uB = (v == 0) ? u20 : ((v == 1) ? u21 : u22);
                float pb = wsum16(dot4(uB, nt));
                if (j < deg) {
                    float pa = sd[j];
                    float sc = pa * pa * pb;
                    if (v == 0)      fma4(A0, sc, nt);
                    else if (v == 1) fma4(A1, sc, nt);
                    else             fma4(A2, sc, nt);
                }
            }
            u30 = make_float4(A0.x * i0 + en.x, A0.y * i0 + en.y, A0.z * i0 + en.z, A0.w * i0 + en.w);
            u31 = make_float4(A1.x * i1 + en.x, A1.y * i1 + en.y, A1.z * i1 + en.z, A1.w * i1 + en.w);
            u32 = make_float4(A2.x * i2 + en.x, A2.y * i2 + en.y, A2.z * i2 + en.z, A2.w * i2 + en.w);
        } else {
            // ---------- generic path (rare mdeg > 16) ----------
            float4 A0 = {0,0,0,0}, A1 = {0,0,0,0}, A2 = {0,0,0,0};
            int c0 = 0, c1 = 0, c2 = 0;
            for (int b = 0; b < mdeg; b += 16) {
                int m = min(16, mdeg - b);
                int idx = b + l16;
                int pk = (idx < deg) ? packed[s + idx] : 0;
                for (int j = 0; j < m; j++) {
                    int p = __shfl_sync(0xffffffffu, pk, j, 16);
                    int t = p & 0x3FFFF, v = p >> 18;
                    float4 nt = ent_in[t * 16 + l16];
                    if (b + j < deg) {
                        if (v == 0)      { add4(A0, nt); c0++; }
                        else if (v == 1) { add4(A1, nt); c1++; }
                        else             { add4(A2, nt); c2++; }
                    }
                }
            }
            float i0 = __fdividef(1.f, fmaxf((float)c0, 1.f));
            float i1 = __fdividef(1.f, fmaxf((float)c1, 1.f));
            float i2 = __fdividef(1.f, fmaxf((float)c2, 1.f));
            float4 u10 = squash_addi4(A0, i0, en);
            float4 u11 = squash_addi4(A1, i1, en);
            float4 u12 = squash_addi4(A2, i2, en);

            A0 = make_float4(0,0,0,0); A1 = make_float4(0,0,0,0); A2 = make_float4(0,0,0,0);
            for (int b = 0; b < mdeg; b += 16) {
                int m = min(16, mdeg - b);
                int idx = b + l16;
                int pk = (idx < deg) ? packed[s + idx] : 0;
                for (int j = 0; j < m; j++) {
                    int p = __shfl_sync(0xffffffffu, pk, j, 16);
                    int t = p & 0x3FFFF, v = p >> 18;
                    float4 nt = ent_in[t * 16 + l16];
                    float4 uv = (v == 0) ? u10 : ((v == 1) ? u11 : u12);
                    float d = wsum16(dot4(uv, nt));
                    if (b + j < deg) {
                        if (v == 0)      fma4(A0, d, nt);
                        else if (v == 1) fma4(A1, d, nt);
                        else             fma4(A2, d, nt);
                    }
                }
            }
            float4 u20 = squash_addi4(A0, i0, en);
            float4 u21 = squash_addi4(A1, i1, en);
            float4 u22 = squash_addi4(A2, i2, en);

            A0 = make_float4(0,0,0,0); A1 = make_float4(0,0,0,0); A2 = make_float4(0,0,0,0);
            for (int b = 0; b < mdeg; b += 16) {
                int m = min(16, mdeg - b);
                int idx = b + l16;
                int pk = (idx < deg) ? packed[s + idx] : 0;
                for (int j = 0; j < m; j++) {
                    int p = __shfl_sync(0xffffffffu, pk, j, 16);
                    int t = p & 0x3FFFF, v = p >> 18;
                    float4 nt = ent_in[t * 16 + l16];
                    float4 uA = (v == 0) ? u10 : ((v == 1) ? u11 : u12);
                    float4 uB = (v == 0) ? u20 : ((v == 1) ? u21 : u22);
                    float pa = dot4(uA, nt);
                    float pb = dot4(uB, nt);
                    #pragma unroll
                    for (int o = 8; o > 0; o >>= 1) {
                        pa += __shfl_xor_sync(0xffffffffu, pa, o);
                        pb += __shfl_xor_sync(0xffffffffu, pb, o);
                    }
                    if (b + j < deg) {
                        float sc = pa * pa * pb;
                        if (v == 0)      fma4(A0, sc, nt);
                        else if (v == 1) fma4(A1, sc, nt);
                        else             fma4(A2, sc, nt);
                    }
                }
            }
            u30 = make_float4(A0.x * i0 + en.x, A0.y * i0 + en.y, A0.z * i0 + en.z, A0.w * i0 + en.w);
            u31 = make_float4(A1.x * i1 + en.x, A1.y * i1 + en.y, A1.z * i1 + en.z, A1.w * i1 + en.w);
            u32 = make_float4(A2.x * i2 + en.x, A2.y * i2 + en.y, A2.z * i2 + en.z, A2.w * i2 + en.w);
        }

        // weighted agg + l2norm + residual
        float4 ag = make_float4(w0 * u30.x + w1 * u31.x + w2 * u32.x,
                                w0 * u30.y + w1 * u31.y + w2 * u32.y,
                                w0 * u30.z + w1 * u31.z + w2 * u32.z,
                                w0 * u30.w + w1 * u31.w + w2 * u32.w);
        float sq = wsum16(dot4(ag, ag));
        float in2 = __fdividef(1.0f, fmaxf(sqrtf(sq), 1e-12f));
        float4 o = make_float4(ag.x * in2, ag.y * in2, ag.z * in2, ag.w * in2);
        if (ent_store) ent_store[w * 16 + l16] = o;
        float4 r;
        if (init) r = make_float4(en.x + o.x, en.y + o.y, en.z + o.z, en.w + o.w);
        else {
            r = res_ent[w * 16 + l16];
            r.x += o.x; r.y += o.y; r.z += o.z; r.w += o.w;
        }
        res_ent[w * 16 + l16] = r;

    } else {
        // ======================= USER (2 degree-matched users / warp) ==========
        int slot = ((blockIdx.x - EBLK) * WPB + wid) * HPW + half;
        int w = g_perm_usr[slot];                        // degree-sorted user id

        float4 un = usr_in[w * 16 + l16];
        int s = off_u[w], e = off_u[w + 1];
        int deg = e - s;
        int mdeg = max(deg, __shfl_xor_sync(0xffffffffu, deg, 16));
        float invd = __fdividef(1.f, fmaxf((float)deg, 1.f));
        float4 u3;

        if (mdeg <= 16) {
            // ---------- fast path ----------
            int it = (l16 < deg) ? items[s + l16] : 0;

            float4 A = {0,0,0,0};
            for (int j = 0; j < mdeg; j++) {
                int t = __shfl_sync(0xffffffffu, it, j, 16);
                float4 nt = ent_in[t * 16 + l16];
                if (j < deg) add4(A, nt);
            }
            float4 u1 = squash_addi4(A, invd, un);

            A = make_float4(0,0,0,0);
            for (int j = 0; j < mdeg; j++) {
                int t = __shfl_sync(0xffffffffu, it, j, 16);
                float4 nt = ent_in[t * 16 + l16];
                float d = wsum16(dot4(u1, nt));
                if (j < deg) fma4(A, d, nt);
            }
            float4 u2 = squash_addi4(A, invd, un);

            A = make_float4(0,0,0,0);
            for (int j = 0; j < mdeg; j++) {
                int t = __shfl_sync(0xffffffffu, it, j, 16);
                float4 nt = ent_in[t * 16 + l16];
                float d = wsum16(dot4(u2, nt));
                if (j < deg) fma4(A, d, nt);
            }
            u3 = make_float4(A.x * invd + un.x, A.y * invd + un.y,
                             A.z * invd + un.z, A.w * invd + un.w);
        } else {
            // ---------- generic path ----------
            float4 A = {0,0,0,0};
            for (int b = 0; b < mdeg; b += 16) {
                int m = min(16, mdeg - b);
                int idx = b + l16;
                int it = (idx < deg) ? items[s + idx] : 0;
                for (int j = 0; j < m; j++) {
                    int t = __shfl_sync(0xffffffffu, it, j, 16);
                    float4 nt = ent_in[t * 16 + l16];
                    if (b + j < deg) add4(A, nt);
                }
            }
            float4 u1 = squash_addi4(A, invd, un);

            A = make_float4(0,0,0,0);
            for (int b = 0; b < mdeg; b += 16) {
                int m = min(16, mdeg - b);
                int idx = b + l16;
                int it = (idx < deg) ? items[s + idx] : 0;
                for (int j = 0; j < m; j++) {
                    int t = __shfl_sync(0xffffffffu, it, j, 16);
                    float4 nt = ent_in[t * 16 + l16];
                    float d = wsum16(dot4(u1, nt));
                    if (b + j < deg) fma4(A, d, nt);
                }
            }
            float4 u2 = squash_addi4(A, invd, un);

            A = make_float4(0,0,0,0);
            for (int b = 0; b < mdeg; b += 16) {
                int m = min(16, mdeg - b);
                int idx = b + l16;
                int it = (idx < deg) ? items[s + idx] : 0;
                for (int j = 0; j < m; j++) {
                    int t = __shfl_sync(0xffffffffu, it, j, 16);
                    float4 nt = ent_in[t * 16 + l16];
                    float d = wsum16(dot4(u2, nt));
                    if (b + j < deg) fma4(A, d, nt);
                }
            }
            u3 = make_float4(A.x * invd + un.x, A.y * invd + un.y,
                             A.z * invd + un.z, A.w * invd + un.w);
        }

        float sq = wsum16(dot4(u3, u3));
        float in2 = __fdividef(1.0f, fmaxf(sqrtf(sq), 1e-12f));
        float4 o = make_float4(u3.x * in2, u3.y * in2, u3.z * in2, u3.w * in2);
        if (usr_store) usr_store[w * 16 + l16] = o;
        float4 r;
        if (init) r = make_float4(un.x + o.x, un.y + o.y, un.z + o.z, un.w + o.w);
        else {
            r = res_usr[w * 16 + l16];
            r.x += o.x; r.y += o.y; r.z += o.z; r.w += o.w;
        }
        res_usr[w * 16 + l16] = r;
    }
}

// ---------------- launch (5 launches) ----------------
extern "C" void kernel_launch(void* const* d_in, const int* in_sizes, int n_in,
                              void* d_out, int out_size) {
    const float* entity_emb = (const float*)d_in[0];
    const float* user_emb   = (const float*)d_in[1];
    const float* latent     = (const float*)d_in[2];
    const float* relw       = (const float*)d_in[3];
    const float* aggw       = (const float*)d_in[4];
    const int*   eidx       = (const int*)d_in[5];   // [2,E]: head row, then tail row
    const int*   etype      = (const int*)d_in[6];
    const int*   uidx       = (const int*)d_in[7];
    const int*   iidx       = (const int*)d_in[8];
    float* out = (float*)d_out;

    int *p_off_ent, *p_off_usr, *p_packed, *p_items;
    float *p_entB, *p_usrB;
    cudaGetSymbolAddress((void**)&p_off_ent, g_off_ent);
    cudaGetSymbolAddress((void**)&p_off_usr, g_off_usr);
    cudaGetSymbolAddress((void**)&p_packed,  g_packed);
    cudaGetSymbolAddress((void**)&p_items,   g_items);
    cudaGetSymbolAddress((void**)&p_entB,    g_entB);
    cudaGetSymbolAddress((void**)&p_usrB,    g_usrB);

    hist_both_k<<<2048, 256>>>(eidx, uidx, relw, latent);                    // #0
    scan_chain_k<<<TILES_E + TILES_U, 1024>>>();                             // #1
    scatter_both_k<<<2048, 256>>>(eidx, eidx + E_N, etype, uidx, iidx);      // #2

    float4* res_e = (float4*)out;
    float4* res_u = (float4*)(out + (size_t)N_ENT * DIM);

    // hop 0 (#3): base embeddings in; init residual; ZBLK tail blocks re-zero cnt
    fused_hop_k<<<EBLK + UBLK + ZBLK, 256>>>(
        (const float4*)entity_emb, (const float4*)user_emb, aggw, 0, 1,
        p_off_ent, p_packed, p_off_usr, p_items,
        (float4*)p_entB, (float4*)p_usrB, res_e, res_u);

    // hop 1 (#4): hop-0 outputs in; accumulate residual only
    fused_hop_k<<<EBLK + UBLK, 256>>>(
        (const float4*)p_entB, (const float4*)p_usrB, aggw, 1, 0,
        p_off_ent, p_packed, p_off_usr, p_items,
        nullptr, nullptr, res_e, res_u);
}